// round 1
// baseline (speedup 1.0000x reference)
#include <cuda_runtime.h>
#include <mma.h>

using namespace nvcuda;

// Problem constants
#define Bn   2
#define Sn   2048
#define EMB  2048
#define NH   16
#define NKV  4
#define DH   128
#define MROWS (Bn*Sn)   // 4096

// Scratch (device globals; no runtime allocation allowed)
__device__ float g_qh[(size_t)Bn*NH*Sn*DH];    // [B,H,S,D]   33.5 MB
__device__ float g_kh[(size_t)Bn*NKV*Sn*DH];   // [B,Hk,S,D]   8.4 MB
__device__ float g_vh[(size_t)Bn*NKV*Sn*DH];   //              8.4 MB
__device__ float g_z [(size_t)Bn*Sn*NH*DH];    // [B,S,H*D]   33.5 MB

__device__ __forceinline__ float tf32r(float x) { return wmma::__float_to_tf32(x); }

// ---------------------------------------------------------------------------
// Generic TF32 GEMM: C = A[M,K] @ W[K,N]
// MODE 0: plain row-major fp32 output
// MODE 1: scatter into per-head layout [B, H, S, D] with scale applied
// BM=128, BN=128, BK=32, 256 threads (8 warps: 2 (m) x 4 (n), warp tile 64x32)
// All shapes used here are multiples of the tiles -> no bounds checks.
// ---------------------------------------------------------------------------
template<int MODE>
__global__ __launch_bounds__(256)
void gemm_tf32(const float* __restrict__ A, const float* __restrict__ W,
               float* __restrict__ C, int M, int N, int K, int H, float scale)
{
    constexpr int BM = 128, BN = 128, BK = 32;
    constexpr int LDA = BK + 4;   // 36 floats
    constexpr int LDB = BN + 4;   // 132 floats
    __shared__ __align__(32) float As[BM * LDA];
    __shared__ __align__(32) float Bs[BK * LDB];
    __shared__ __align__(32) float stage[8 * 16 * 20];

    const int tid  = threadIdx.x;
    const int wid  = tid >> 5;
    const int lane = tid & 31;
    const int m0 = blockIdx.y * BM;
    const int n0 = blockIdx.x * BN;
    const int wm = (wid & 1) * 64;
    const int wn = (wid >> 1) * 32;

    wmma::fragment<wmma::accumulator, 16, 16, 8, float> acc[4][2];
    #pragma unroll
    for (int i = 0; i < 4; i++)
        #pragma unroll
        for (int j = 0; j < 2; j++)
            wmma::fill_fragment(acc[i][j], 0.0f);

    for (int k0 = 0; k0 < K; k0 += BK) {
        // Load A tile 128x32 (fp32 -> tf32)
        #pragma unroll
        for (int it = 0; it < 4; ++it) {
            int e = tid + it * 256;       // 0..1023 float4 slots
            int r = e >> 3, c = (e & 7) << 2;
            float4 v = *reinterpret_cast<const float4*>(A + (size_t)(m0 + r) * K + k0 + c);
            float4 t; t.x = tf32r(v.x); t.y = tf32r(v.y); t.z = tf32r(v.z); t.w = tf32r(v.w);
            *reinterpret_cast<float4*>(As + r * LDA + c) = t;
        }
        // Load B tile 32x128
        #pragma unroll
        for (int it = 0; it < 4; ++it) {
            int e = tid + it * 256;
            int r = e >> 5, c = (e & 31) << 2;
            float4 v = *reinterpret_cast<const float4*>(W + (size_t)(k0 + r) * N + n0 + c);
            float4 t; t.x = tf32r(v.x); t.y = tf32r(v.y); t.z = tf32r(v.z); t.w = tf32r(v.w);
            *reinterpret_cast<float4*>(Bs + r * LDB + c) = t;
        }
        __syncthreads();

        #pragma unroll
        for (int kk = 0; kk < BK; kk += 8) {
            wmma::fragment<wmma::matrix_a, 16, 16, 8, wmma::precision::tf32, wmma::row_major> af[4];
            wmma::fragment<wmma::matrix_b, 16, 16, 8, wmma::precision::tf32, wmma::row_major> bf[2];
            #pragma unroll
            for (int i = 0; i < 4; i++)
                wmma::load_matrix_sync(af[i], As + (wm + i * 16) * LDA + kk, LDA);
            #pragma unroll
            for (int j = 0; j < 2; j++)
                wmma::load_matrix_sync(bf[j], Bs + kk * LDB + wn + j * 16, LDB);
            #pragma unroll
            for (int i = 0; i < 4; i++)
                #pragma unroll
                for (int j = 0; j < 2; j++)
                    wmma::mma_sync(acc[i][j], af[i], bf[j], acc[i][j]);
        }
        __syncthreads();
    }

    // Epilogue: per-warp staging, then indexed global writes
    float* st = stage + wid * 16 * 20;
    #pragma unroll
    for (int i = 0; i < 4; i++) {
        #pragma unroll
        for (int j = 0; j < 2; j++) {
            wmma::store_matrix_sync(st, acc[i][j], 20, wmma::mem_row_major);
            __syncwarp();
            #pragma unroll
            for (int e = lane; e < 256; e += 32) {
                int r = e >> 4, c = e & 15;
                float v = st[r * 20 + c];
                int gr = m0 + wm + i * 16 + r;
                int gc = n0 + wn + j * 16 + c;
                if (MODE == 0) {
                    C[(size_t)gr * N + gc] = v;
                } else {
                    int bb = gr >> 11;          // / Sn
                    int ss = gr & (Sn - 1);
                    int hh = gc >> 7;           // / DH
                    int dd = gc & (DH - 1);
                    C[(((size_t)bb * H + hh) * Sn + ss) * DH + dd] = v * scale;
                }
            }
            __syncwarp();
        }
    }
}

// ---------------------------------------------------------------------------
// Flash-attention (causal) with TF32 wmma, 64-row q tile, 64-col k tiles.
// O accumulator kept in smem fp32 (row-addressable for online-softmax rescale).
// Grid: (S/64, NH, B). 256 threads.
// ---------------------------------------------------------------------------
__global__ __launch_bounds__(256)
void attn_kernel(const float* __restrict__ qh, const float* __restrict__ kh,
                 const float* __restrict__ vh, float* __restrict__ z)
{
    constexpr int LD  = 132;   // 128 + 4 pad (fp32)
    constexpr int LDS = 68;    // 64 + 4 pad
    extern __shared__ __align__(32) float sm[];
    float* Qs   = sm;                 // 64*132
    float* Ks   = Qs + 64 * LD;       // 64*132
    float* Vs   = Ks + 64 * LD;       // 64*132
    float* Os   = Vs + 64 * LD;       // 64*132
    float* Ss   = Os + 64 * LD;       // 64*68  (scores, then P in-place)
    float* mrow = Ss + 64 * LDS;      // 64
    float* lrow = mrow + 64;          // 64

    const int qt = blockIdx.x;
    const int h  = blockIdx.y;
    const int b  = blockIdx.z;
    const int hk = h >> 2;            // GQA: 4 q-heads per kv head
    const int q0 = qt * 64;
    const int tid = threadIdx.x;
    const int wid = tid >> 5;

    const float* Qg = qh + (((size_t)b * NH  + h ) * Sn + q0) * DH;
    const float* Kg = kh + ((size_t)b * NKV + hk) * Sn * DH;
    const float* Vg = vh + ((size_t)b * NKV + hk) * Sn * DH;

    // Load Q tile, zero O
    #pragma unroll
    for (int it = 0; it < 8; ++it) {
        int e = tid + it * 256;       // 2048 float4 slots = 64x128
        int r = e >> 5, c = (e & 31) << 2;
        float4 v = *reinterpret_cast<const float4*>(Qg + (size_t)r * DH + c);
        float4 t; t.x = tf32r(v.x); t.y = tf32r(v.y); t.z = tf32r(v.z); t.w = tf32r(v.w);
        *reinterpret_cast<float4*>(Qs + r * LD + c) = t;
        float4 zz = make_float4(0.f, 0.f, 0.f, 0.f);
        *reinterpret_cast<float4*>(Os + r * LD + c) = zz;
    }
    if (tid < 64) { mrow[tid] = -1e30f; lrow[tid] = 0.0f; }
    __syncthreads();

    for (int kt = 0; kt <= qt; ++kt) {
        const int diag = (kt == qt);
        const size_t koff = (size_t)kt * 64 * DH;

        // Load K, V tiles
        #pragma unroll
        for (int it = 0; it < 8; ++it) {
            int e = tid + it * 256;
            int r = e >> 5, c = (e & 31) << 2;
            float4 kv = *reinterpret_cast<const float4*>(Kg + koff + (size_t)r * DH + c);
            float4 vv = *reinterpret_cast<const float4*>(Vg + koff + (size_t)r * DH + c);
            float4 tk; tk.x = tf32r(kv.x); tk.y = tf32r(kv.y); tk.z = tf32r(kv.z); tk.w = tf32r(kv.w);
            float4 tv; tv.x = tf32r(vv.x); tv.y = tf32r(vv.y); tv.z = tf32r(vv.z); tv.w = tf32r(vv.w);
            *reinterpret_cast<float4*>(Ks + r * LD + c) = tk;
            *reinterpret_cast<float4*>(Vs + r * LD + c) = tv;
        }
        __syncthreads();

        // S = Q . K^T  (64x64): 16 tiles, 2 per warp
        #pragma unroll
        for (int t2 = 0; t2 < 2; ++t2) {
            int t  = wid * 2 + t2;
            int tm = t >> 2, tn = t & 3;
            wmma::fragment<wmma::accumulator, 16, 16, 8, float> cfr;
            wmma::fill_fragment(cfr, 0.0f);
            #pragma unroll
            for (int k = 0; k < DH; k += 8) {
                wmma::fragment<wmma::matrix_a, 16, 16, 8, wmma::precision::tf32, wmma::row_major> a;
                wmma::fragment<wmma::matrix_b, 16, 16, 8, wmma::precision::tf32, wmma::col_major> bfr;
                wmma::load_matrix_sync(a,   Qs + tm * 16 * LD + k, LD);
                wmma::load_matrix_sync(bfr, Ks + tn * 16 * LD + k, LD);  // B(d,j)=K[j][d]
                wmma::mma_sync(cfr, a, bfr, cfr);
            }
            wmma::store_matrix_sync(Ss + tm * 16 * LDS + tn * 16, cfr, LDS, wmma::mem_row_major);
        }
        __syncthreads();

        // Online softmax: 4 threads per row, 16 cols each
        {
            int r  = tid >> 2;
            int q4 = tid & 3;
            float* srow = Ss + r * LDS;
            int vmax = diag ? (r + 1) : 64;   // # valid columns (causal)
            float tmax = -1e30f;
            #pragma unroll
            for (int jj = 0; jj < 16; ++jj) {
                int j = q4 * 16 + jj;
                float sv = (j < vmax) ? srow[j] : -1e30f;
                tmax = fmaxf(tmax, sv);
            }
            tmax = fmaxf(tmax, __shfl_xor_sync(0xffffffffu, tmax, 1));
            tmax = fmaxf(tmax, __shfl_xor_sync(0xffffffffu, tmax, 2));
            float mprev = mrow[r];
            float mnew  = fmaxf(mprev, tmax);
            float alpha = __expf(mprev - mnew);
            float lsum = 0.0f;
            #pragma unroll
            for (int jj = 0; jj < 16; ++jj) {
                int j = q4 * 16 + jj;
                float p = (j < vmax) ? __expf(srow[j] - mnew) : 0.0f;
                srow[j] = tf32r(p);           // P in place of S
                lsum += p;
            }
            lsum += __shfl_xor_sync(0xffffffffu, lsum, 1);
            lsum += __shfl_xor_sync(0xffffffffu, lsum, 2);
            if (q4 == 0) { mrow[r] = mnew; lrow[r] = lrow[r] * alpha + lsum; }
            // rescale O row
            float* orow = Os + r * LD + q4 * 32;
            #pragma unroll
            for (int c2 = 0; c2 < 32; ++c2) orow[c2] *= alpha;
        }
        __syncthreads();

        // O += P . V  (64x128): 32 tiles, 4 per warp
        #pragma unroll
        for (int t4 = 0; t4 < 4; ++t4) {
            int t  = wid * 4 + t4;
            int tm = t >> 3, tn = t & 7;
            wmma::fragment<wmma::accumulator, 16, 16, 8, float> cfr;
            wmma::load_matrix_sync(cfr, Os + tm * 16 * LD + tn * 16, LD, wmma::mem_row_major);
            #pragma unroll
            for (int k = 0; k < 64; k += 8) {
                wmma::fragment<wmma::matrix_a, 16, 16, 8, wmma::precision::tf32, wmma::row_major> a;
                wmma::fragment<wmma::matrix_b, 16, 16, 8, wmma::precision::tf32, wmma::row_major> bfr;
                wmma::load_matrix_sync(a,   Ss + tm * 16 * LDS + k, LDS);
                wmma::load_matrix_sync(bfr, Vs + k * LD + tn * 16, LD);
                wmma::mma_sync(cfr, a, bfr, cfr);
            }
            wmma::store_matrix_sync(Os + tm * 16 * LD + tn * 16, cfr, LD, wmma::mem_row_major);
        }
        __syncthreads();
    }

    // Normalize and write Z[b, s, h*DH + d]
    float* zb = z + ((size_t)b * Sn + q0) * (NH * DH) + h * DH;
    #pragma unroll
    for (int it = 0; it < 8; ++it) {
        int e = tid + it * 256;
        int r = e >> 5, c = (e & 31) << 2;
        float inv = 1.0f / lrow[r];
        float4 o;
        o.x = Os[r * LD + c + 0] * inv;
        o.y = Os[r * LD + c + 1] * inv;
        o.z = Os[r * LD + c + 2] * inv;
        o.w = Os[r * LD + c + 3] * inv;
        *reinterpret_cast<float4*>(zb + (size_t)r * (NH * DH) + c) = o;
    }
}

// ---------------------------------------------------------------------------
extern "C" void kernel_launch(void* const* d_in, const int* in_sizes, int n_in,
                              void* d_out, int out_size)
{
    const float* q  = (const float*)d_in[0];
    const float* k  = (const float*)d_in[1];
    const float* v  = (const float*)d_in[2];
    const float* Wq = (const float*)d_in[3];
    const float* Wk = (const float*)d_in[4];
    const float* Wv = (const float*)d_in[5];
    const float* Wo = (const float*)d_in[6];
    float* out = (float*)d_out;

    float *qh, *khp, *vhp, *zbuf;
    cudaGetSymbolAddress((void**)&qh,  g_qh);
    cudaGetSymbolAddress((void**)&khp, g_kh);
    cudaGetSymbolAddress((void**)&vhp, g_vh);
    cudaGetSymbolAddress((void**)&zbuf, g_z);

    const float scale = 0.29730177875068026f;  // 128^-0.25 (applied to Q and K)

    dim3 blk(256);
    // Projections (scatter to [B,H,S,D])
    gemm_tf32<1><<<dim3(EMB / 128,        MROWS / 128), blk>>>(q, Wq, qh,  MROWS, EMB,      EMB, NH,  scale);
    gemm_tf32<1><<<dim3((NKV*DH) / 128,   MROWS / 128), blk>>>(k, Wk, khp, MROWS, NKV * DH, EMB, NKV, scale);
    gemm_tf32<1><<<dim3((NKV*DH) / 128,   MROWS / 128), blk>>>(v, Wv, vhp, MROWS, NKV * DH, EMB, NKV, 1.0f);

    // Attention
    const int smemBytes = (4 * 64 * 132 + 64 * 68 + 128) * (int)sizeof(float);  // 153088
    cudaFuncSetAttribute(attn_kernel, cudaFuncAttributeMaxDynamicSharedMemorySize, smemBytes);
    attn_kernel<<<dim3(Sn / 64, NH, Bn), blk, smemBytes>>>(qh, khp, vhp, zbuf);

    // Output projection
    gemm_tf32<0><<<dim3(EMB / 128, MROWS / 128), blk>>>(zbuf, Wo, out, MROWS, EMB, EMB, 0, 1.0f);
}

// round 2
// speedup vs baseline: 1.3694x; 1.3694x over previous
#include <cuda_runtime.h>
#include <mma.h>
#include <cstdint>

using namespace nvcuda;

// Problem constants
#define Bn   2
#define Sn   2048
#define EMB  2048
#define NH   16
#define NKV  4
#define DH   128
#define MROWS (Bn*Sn)   // 4096

// Scratch (device globals; no runtime allocation allowed)
__device__ float g_qh[(size_t)Bn*NH*Sn*DH];    // [B,H,S,D]
__device__ float g_kh[(size_t)Bn*NKV*Sn*DH];   // [B,Hk,S,D]
__device__ float g_vh[(size_t)Bn*NKV*Sn*DH];
__device__ float g_z [(size_t)Bn*Sn*NH*DH];    // [B,S,H*D]

__device__ __forceinline__ float tf32f(float x) { return wmma::__float_to_tf32(x); }
__device__ __forceinline__ uint32_t f2tf(float x) {
    uint32_t r; asm("cvt.rna.tf32.f32 %0, %1;" : "=r"(r) : "f"(x)); return r;
}
__device__ __forceinline__ void mma_tf32(float c[4], const uint32_t a[4], uint32_t b0, uint32_t b1) {
    asm volatile("mma.sync.aligned.m16n8k8.row.col.f32.tf32.tf32.f32 "
        "{%0,%1,%2,%3},{%4,%5,%6,%7},{%8,%9},{%0,%1,%2,%3};"
        : "+f"(c[0]), "+f"(c[1]), "+f"(c[2]), "+f"(c[3])
        : "r"(a[0]), "r"(a[1]), "r"(a[2]), "r"(a[3]), "r"(b0), "r"(b1));
}
__device__ __forceinline__ void cp_async16(uint32_t saddr, const float* gptr) {
    asm volatile("cp.async.ca.shared.global [%0], [%1], 16;\n"
        :: "r"(saddr), "l"(__cvta_generic_to_global(gptr)));
}
__device__ __forceinline__ void cp_async_commit() { asm volatile("cp.async.commit_group;\n"); }
__device__ __forceinline__ void cp_async_wait0()  { asm volatile("cp.async.wait_group 0;\n"); }

// ---------------------------------------------------------------------------
// TF32 GEMM: C = A[M,K] @ W[K,N], double-buffered smem.
// MODE 0: plain row-major fp32 output
// MODE 1: scatter into per-head layout [B, H, S, D] with scale applied
// BM=128, BN=128, BK=32, 256 threads (8 warps: 2(m) x 4(n), warp tile 64x32)
// ---------------------------------------------------------------------------
template<int MODE>
__global__ __launch_bounds__(256)
void gemm_tf32(const float* __restrict__ A, const float* __restrict__ W,
               float* __restrict__ C, int M, int N, int K, int H, float scale)
{
    constexpr int BM = 128, BN = 128, BK = 32;
    constexpr int LDA = BK + 4;   // 36
    constexpr int LDB = BN + 4;   // 132
    extern __shared__ float smg[];
    float* As    = smg;                    // 2 * 128*36
    float* Bs    = smg + 2 * BM * LDA;     // 2 * 32*132
    float* stage = Bs  + 2 * BK * LDB;     // 8*16*20

    const int tid  = threadIdx.x;
    const int wid  = tid >> 5;
    const int lane = tid & 31;
    const int m0 = blockIdx.y * BM;
    const int n0 = blockIdx.x * BN;
    const int wm = (wid & 1) * 64;
    const int wn = (wid >> 1) * 32;

    wmma::fragment<wmma::accumulator, 16, 16, 8, float> acc[4][2];
    #pragma unroll
    for (int i = 0; i < 4; i++)
        #pragma unroll
        for (int j = 0; j < 2; j++)
            wmma::fill_fragment(acc[i][j], 0.0f);

    float4 ra[4], rb[4];
    auto ldg_tile = [&](int k0) {
        #pragma unroll
        for (int it = 0; it < 4; ++it) {
            int e = tid + it * 256;       // A: 128x32 -> 1024 float4
            int r = e >> 3, c = (e & 7) << 2;
            ra[it] = *reinterpret_cast<const float4*>(A + (size_t)(m0 + r) * K + k0 + c);
        }
        #pragma unroll
        for (int it = 0; it < 4; ++it) {
            int e = tid + it * 256;       // B: 32x128
            int r = e >> 5, c = (e & 31) << 2;
            rb[it] = *reinterpret_cast<const float4*>(W + (size_t)(k0 + r) * N + n0 + c);
        }
    };
    auto sts_tile = [&](int bsel) {
        float* Ab = As + bsel * BM * LDA;
        float* Bb = Bs + bsel * BK * LDB;
        #pragma unroll
        for (int it = 0; it < 4; ++it) {
            int e = tid + it * 256;
            int r = e >> 3, c = (e & 7) << 2;
            float4 t; t.x = tf32f(ra[it].x); t.y = tf32f(ra[it].y);
            t.z = tf32f(ra[it].z); t.w = tf32f(ra[it].w);
            *reinterpret_cast<float4*>(Ab + r * LDA + c) = t;
        }
        #pragma unroll
        for (int it = 0; it < 4; ++it) {
            int e = tid + it * 256;
            int r = e >> 5, c = (e & 31) << 2;
            float4 t; t.x = tf32f(rb[it].x); t.y = tf32f(rb[it].y);
            t.z = tf32f(rb[it].z); t.w = tf32f(rb[it].w);
            *reinterpret_cast<float4*>(Bb + r * LDB + c) = t;
        }
    };

    ldg_tile(0);
    sts_tile(0);
    __syncthreads();

    const int nIter = K / BK;
    int buf = 0;
    for (int it = 0; it < nIter; ++it) {
        if (it + 1 < nIter) ldg_tile((it + 1) * BK);

        const float* Ab = As + buf * BM * LDA;
        const float* Bb = Bs + buf * BK * LDB;
        #pragma unroll
        for (int kk = 0; kk < BK; kk += 8) {
            wmma::fragment<wmma::matrix_a, 16, 16, 8, wmma::precision::tf32, wmma::row_major> af[4];
            wmma::fragment<wmma::matrix_b, 16, 16, 8, wmma::precision::tf32, wmma::row_major> bf[2];
            #pragma unroll
            for (int i = 0; i < 4; i++)
                wmma::load_matrix_sync(af[i], Ab + (wm + i * 16) * LDA + kk, LDA);
            #pragma unroll
            for (int j = 0; j < 2; j++)
                wmma::load_matrix_sync(bf[j], Bb + kk * LDB + wn + j * 16, LDB);
            #pragma unroll
            for (int i = 0; i < 4; i++)
                #pragma unroll
                for (int j = 0; j < 2; j++)
                    wmma::mma_sync(acc[i][j], af[i], bf[j], acc[i][j]);
        }

        if (it + 1 < nIter) sts_tile(buf ^ 1);
        __syncthreads();
        buf ^= 1;
    }

    // Epilogue: per-warp staging, then indexed global writes
    float* st = stage + wid * 16 * 20;
    #pragma unroll
    for (int i = 0; i < 4; i++) {
        #pragma unroll
        for (int j = 0; j < 2; j++) {
            wmma::store_matrix_sync(st, acc[i][j], 20, wmma::mem_row_major);
            __syncwarp();
            #pragma unroll
            for (int e = lane; e < 256; e += 32) {
                int r = e >> 4, c = e & 15;
                float v = st[r * 20 + c];
                int gr = m0 + wm + i * 16 + r;
                int gc = n0 + wn + j * 16 + c;
                if (MODE == 0) {
                    C[(size_t)gr * N + gc] = v;
                } else {
                    int bb = gr >> 11;          // / Sn
                    int ss = gr & (Sn - 1);
                    int hh = gc >> 7;           // / DH
                    int dd = gc & (DH - 1);
                    C[(((size_t)bb * H + hh) * Sn + ss) * DH + dd] = v * scale;
                }
            }
            __syncwarp();
        }
    }
}

// ---------------------------------------------------------------------------
// Flash attention v2: 128 q-rows/CTA, 64-key tiles, mma.sync m16n8k8 tf32.
// Q and O live in registers; K/V double-buffered in smem via cp.async,
// converted to tf32 (cvt.rna) in place. P relayout via shuffles (no smem).
// Grid: (S/128, NH, B). 256 threads (8 warps x 16 rows).
// ---------------------------------------------------------------------------
#define LDK 132

__global__ __launch_bounds__(256, 1)
void attn2(const float* __restrict__ qh, const float* __restrict__ kh,
           const float* __restrict__ vh, float* __restrict__ z)
{
    extern __shared__ float sm[];   // 2 bufs x (K 64x132 + V 64x132)
    const int tid  = threadIdx.x;
    const int lane = tid & 31;
    const int w    = tid >> 5;
    const int g    = lane >> 2;   // groupID (0..7)
    const int tg   = lane & 3;    // thread-in-group

    const int qblk = blockIdx.x;
    const int h    = blockIdx.y;
    const int b    = blockIdx.z;
    const int hk   = h >> 2;
    const int q0   = qblk * 128;

    const float* Qg = qh + (((size_t)b * NH  + h ) * Sn + q0) * DH;
    const float* Kg = kh + ((size_t)b * NKV + hk) * Sn * DH;
    const float* Vg = vh + ((size_t)b * NKV + hk) * Sn * DH;

    const uint32_t smbase = (uint32_t)__cvta_generic_to_shared(sm);
    constexpr int BUFF = 2 * 64 * LDK;           // floats per buffer (K+V)

    auto load_kv_async = [&](int bsel, int kt) {
        uint32_t base = smbase + (uint32_t)(bsel * BUFF) * 4u;
        const float* Kt = Kg + (size_t)kt * 64 * DH;
        const float* Vt = Vg + (size_t)kt * 64 * DH;
        #pragma unroll
        for (int it = 0; it < 8; ++it) {
            int e = tid + it * 256;   // 2048 float4 slots (64x128)
            int r = e >> 5, c = (e & 31) << 2;
            cp_async16(base + (uint32_t)(r * LDK + c) * 4u,            Kt + (size_t)r * DH + c);
            cp_async16(base + (uint32_t)(64 * LDK + r * LDK + c) * 4u, Vt + (size_t)r * DH + c);
        }
        cp_async_commit();
    };

    // Q fragments (one-time strided LDG + cvt.rna)
    uint32_t Qa[16][4];
    {
        const float* qw = Qg + (size_t)(w * 16) * DH;
        #pragma unroll
        for (int ks = 0; ks < 16; ++ks) {
            Qa[ks][0] = f2tf(qw[(size_t)(g    ) * DH + ks * 8 + tg    ]);
            Qa[ks][1] = f2tf(qw[(size_t)(g + 8) * DH + ks * 8 + tg    ]);
            Qa[ks][2] = f2tf(qw[(size_t)(g    ) * DH + ks * 8 + tg + 4]);
            Qa[ks][3] = f2tf(qw[(size_t)(g + 8) * DH + ks * 8 + tg + 4]);
        }
    }

    float O[16][4];
    #pragma unroll
    for (int nv = 0; nv < 16; ++nv)
        #pragma unroll
        for (int i = 0; i < 4; ++i) O[nv][i] = 0.0f;
    float m0 = -1e30f, m1 = -1e30f, l0 = 0.0f, l1 = 0.0f;

    const int ktmax = 2 * qblk + 1;

    load_kv_async(0, 0);
    cp_async_wait0();
    __syncthreads();

    int buf = 0;
    for (int kt = 0; kt <= ktmax; ++kt) {
        float* Ks = sm + buf * BUFF;
        float* Vs = Ks + 64 * LDK;

        if (kt < ktmax) load_kv_async(buf ^ 1, kt + 1);

        // In-place fp32 -> tf32 (round-to-nearest) conversion of current buffer
        #pragma unroll
        for (int it = 0; it < 8; ++it) {
            int e = tid + it * 256;
            int r = e >> 5, c = (e & 31) << 2;
            float4* pk = reinterpret_cast<float4*>(Ks + r * LDK + c);
            float4 a = *pk;
            a.x = tf32f(a.x); a.y = tf32f(a.y); a.z = tf32f(a.z); a.w = tf32f(a.w);
            *pk = a;
            float4* pv = reinterpret_cast<float4*>(Vs + r * LDK + c);
            float4 bfv = *pv;
            bfv.x = tf32f(bfv.x); bfv.y = tf32f(bfv.y); bfv.z = tf32f(bfv.z); bfv.w = tf32f(bfv.w);
            *pv = bfv;
        }
        __syncthreads();

        // ---- S = Q K^T : per warp 16x64, 8 n-tiles ----
        float S[8][4];
        #pragma unroll
        for (int n = 0; n < 8; ++n)
            #pragma unroll
            for (int i = 0; i < 4; ++i) S[n][i] = 0.0f;

        #pragma unroll
        for (int ks = 0; ks < 16; ++ks) {
            #pragma unroll
            for (int n = 0; n < 8; ++n) {
                const float* kp = Ks + (n * 8 + g) * LDK + ks * 8 + tg;
                uint32_t b0 = __float_as_uint(kp[0]);
                uint32_t b1 = __float_as_uint(kp[4]);
                mma_tf32(S[n], Qa[ks], b0, b1);
            }
        }

        // ---- causal mask + online softmax (registers) ----
        const int grow0 = q0 + w * 16 + g;
        const int grow1 = grow0 + 8;
        const int kb = kt * 64;
        float mx0 = -1e30f, mx1 = -1e30f;
        #pragma unroll
        for (int n = 0; n < 8; ++n) {
            int c = kb + n * 8 + 2 * tg;
            if (c     > grow0) S[n][0] = -1e30f;
            if (c + 1 > grow0) S[n][1] = -1e30f;
            if (c     > grow1) S[n][2] = -1e30f;
            if (c + 1 > grow1) S[n][3] = -1e30f;
            mx0 = fmaxf(mx0, fmaxf(S[n][0], S[n][1]));
            mx1 = fmaxf(mx1, fmaxf(S[n][2], S[n][3]));
        }
        mx0 = fmaxf(mx0, __shfl_xor_sync(0xffffffffu, mx0, 1));
        mx0 = fmaxf(mx0, __shfl_xor_sync(0xffffffffu, mx0, 2));
        mx1 = fmaxf(mx1, __shfl_xor_sync(0xffffffffu, mx1, 1));
        mx1 = fmaxf(mx1, __shfl_xor_sync(0xffffffffu, mx1, 2));

        float mn0 = fmaxf(m0, mx0), mn1 = fmaxf(m1, mx1);
        float al0 = __expf(m0 - mn0), al1 = __expf(m1 - mn1);
        m0 = mn0; m1 = mn1;

        float s0 = 0.0f, s1 = 0.0f;
        #pragma unroll
        for (int n = 0; n < 8; ++n) {
            S[n][0] = __expf(S[n][0] - mn0); s0 += S[n][0];
            S[n][1] = __expf(S[n][1] - mn0); s0 += S[n][1];
            S[n][2] = __expf(S[n][2] - mn1); s1 += S[n][2];
            S[n][3] = __expf(S[n][3] - mn1); s1 += S[n][3];
        }
        s0 += __shfl_xor_sync(0xffffffffu, s0, 1);
        s0 += __shfl_xor_sync(0xffffffffu, s0, 2);
        s1 += __shfl_xor_sync(0xffffffffu, s1, 1);
        s1 += __shfl_xor_sync(0xffffffffu, s1, 2);
        l0 = l0 * al0 + s0;
        l1 = l1 * al1 + s1;

        #pragma unroll
        for (int nv = 0; nv < 16; ++nv) {
            O[nv][0] *= al0; O[nv][1] *= al0;
            O[nv][2] *= al1; O[nv][3] *= al1;
        }

        // ---- O += P V : relayout P via shuffles, then 16 n-tiles over DH ----
        #pragma unroll
        for (int ks = 0; ks < 8; ++ks) {
            int srcA = (lane & ~3) | (tg >> 1);
            int srcB = srcA + 2;
            float x0 = __shfl_sync(0xffffffffu, S[ks][0], srcA);
            float x1 = __shfl_sync(0xffffffffu, S[ks][1], srcA);
            float x2 = __shfl_sync(0xffffffffu, S[ks][2], srcA);
            float x3 = __shfl_sync(0xffffffffu, S[ks][3], srcA);
            float y0 = __shfl_sync(0xffffffffu, S[ks][0], srcB);
            float y1 = __shfl_sync(0xffffffffu, S[ks][1], srcB);
            float y2 = __shfl_sync(0xffffffffu, S[ks][2], srcB);
            float y3 = __shfl_sync(0xffffffffu, S[ks][3], srcB);
            bool odd = (tg & 1) != 0;
            uint32_t a[4];
            a[0] = f2tf(odd ? x1 : x0);
            a[1] = f2tf(odd ? x3 : x2);
            a[2] = f2tf(odd ? y1 : y0);
            a[3] = f2tf(odd ? y3 : y2);
            #pragma unroll
            for (int nv = 0; nv < 16; ++nv) {
                uint32_t b0 = __float_as_uint(Vs[(ks * 8 + tg    ) * LDK + nv * 8 + g]);
                uint32_t b1 = __float_as_uint(Vs[(ks * 8 + tg + 4) * LDK + nv * 8 + g]);
                mma_tf32(O[nv], a, b0, b1);
            }
        }

        cp_async_wait0();
        __syncthreads();
        buf ^= 1;
    }

    // ---- normalize and write Z[b, s, h*DH + d] ----
    float inv0 = 1.0f / l0;
    float inv1 = 1.0f / l1;
    float* zp = z + ((size_t)b * Sn + q0 + w * 16) * (NH * DH) + h * DH;
    #pragma unroll
    for (int nv = 0; nv < 16; ++nv) {
        int c = nv * 8 + 2 * tg;
        float2 v0; v0.x = O[nv][0] * inv0; v0.y = O[nv][1] * inv0;
        float2 v1; v1.x = O[nv][2] * inv1; v1.y = O[nv][3] * inv1;
        *reinterpret_cast<float2*>(zp + (size_t)(g    ) * (NH * DH) + c) = v0;
        *reinterpret_cast<float2*>(zp + (size_t)(g + 8) * (NH * DH) + c) = v1;
    }
}

// ---------------------------------------------------------------------------
extern "C" void kernel_launch(void* const* d_in, const int* in_sizes, int n_in,
                              void* d_out, int out_size)
{
    const float* q  = (const float*)d_in[0];
    const float* k  = (const float*)d_in[1];
    const float* v  = (const float*)d_in[2];
    const float* Wq = (const float*)d_in[3];
    const float* Wk = (const float*)d_in[4];
    const float* Wv = (const float*)d_in[5];
    const float* Wo = (const float*)d_in[6];
    float* out = (float*)d_out;

    float *qh, *khp, *vhp, *zbuf;
    cudaGetSymbolAddress((void**)&qh,  g_qh);
    cudaGetSymbolAddress((void**)&khp, g_kh);
    cudaGetSymbolAddress((void**)&vhp, g_vh);
    cudaGetSymbolAddress((void**)&zbuf, g_z);

    const float scale = 0.29730177875068026f;  // 128^-0.25 (applied to Q and K)

    const int smemGemm = (2 * 128 * 36 + 2 * 32 * 132 + 8 * 16 * 20) * (int)sizeof(float); // 80896
    cudaFuncSetAttribute(gemm_tf32<0>, cudaFuncAttributeMaxDynamicSharedMemorySize, smemGemm);
    cudaFuncSetAttribute(gemm_tf32<1>, cudaFuncAttributeMaxDynamicSharedMemorySize, smemGemm);
    const int smemAttn = 2 * 2 * 64 * LDK * (int)sizeof(float);  // 135168
    cudaFuncSetAttribute(attn2, cudaFuncAttributeMaxDynamicSharedMemorySize, smemAttn);

    dim3 blk(256);
    gemm_tf32<1><<<dim3(EMB / 128,      MROWS / 128), blk, smemGemm>>>(q, Wq, qh,  MROWS, EMB,      EMB, NH,  scale);
    gemm_tf32<1><<<dim3((NKV*DH) / 128, MROWS / 128), blk, smemGemm>>>(k, Wk, khp, MROWS, NKV * DH, EMB, NKV, scale);
    gemm_tf32<1><<<dim3((NKV*DH) / 128, MROWS / 128), blk, smemGemm>>>(v, Wv, vhp, MROWS, NKV * DH, EMB, NKV, 1.0f);

    attn2<<<dim3(Sn / 128, NH, Bn), blk, smemAttn>>>(qh, khp, vhp, zbuf);

    gemm_tf32<0><<<dim3(EMB / 128, MROWS / 128), blk, smemGemm>>>(zbuf, Wo, out, MROWS, EMB, EMB, 0, 1.0f);
}

// round 4
// speedup vs baseline: 2.4173x; 1.7653x over previous
#include <cuda_runtime.h>
#include <cstdint>

// Problem constants
#define Bn   2
#define Sn   2048
#define EMB  2048
#define NH   16
#define NKV  4
#define DH   128
#define MROWS (Bn*Sn)   // 4096

// Scratch (device globals; no runtime allocation allowed)
__device__ float g_qh[(size_t)Bn*NH*Sn*DH];    // [B,H,S,D]
__device__ float g_kh[(size_t)Bn*NKV*Sn*DH];   // [B,Hk,S,D]
__device__ float g_vh[(size_t)Bn*NKV*Sn*DH];
__device__ float g_z [(size_t)Bn*Sn*NH*DH];    // [B,S,H*D]

__device__ __forceinline__ uint32_t f2tf(float x) {
    uint32_t r; asm("cvt.rna.tf32.f32 %0, %1;" : "=r"(r) : "f"(x)); return r;
}
__device__ __forceinline__ void mma_tf32(float c[4], const uint32_t a[4], uint32_t b0, uint32_t b1) {
    asm volatile("mma.sync.aligned.m16n8k8.row.col.f32.tf32.tf32.f32 "
        "{%0,%1,%2,%3},{%4,%5,%6,%7},{%8,%9},{%0,%1,%2,%3};"
        : "+f"(c[0]), "+f"(c[1]), "+f"(c[2]), "+f"(c[3])
        : "r"(a[0]), "r"(a[1]), "r"(a[2]), "r"(a[3]), "r"(b0), "r"(b1));
}
__device__ __forceinline__ void cp_async16(uint32_t saddr, const float* gptr) {
    asm volatile("cp.async.ca.shared.global [%0], [%1], 16;\n"
        :: "r"(saddr), "l"(__cvta_generic_to_global(gptr)));
}
__device__ __forceinline__ void cp_async_commit() { asm volatile("cp.async.commit_group;\n"); }
__device__ __forceinline__ void cp_async_wait0()  { asm volatile("cp.async.wait_group 0;\n"); }
__device__ __forceinline__ void cp_async_wait1()  { asm volatile("cp.async.wait_group 1;\n"); }

// ---------------------------------------------------------------------------
// TF32 GEMM: C = A[M,K] @ W[K,N]. 3-stage cp.async pipeline, raw fp32 smem,
// cvt.rna at operand load, direct mma.sync epilogue (no staging).
// BM=128, BN=128, BK=32, 256 threads; 8 warps = 4(m) x 2(n); warp tile 32x64.
// MODE 0: row-major output; MODE 1: scatter to [B,H,S,D] with scale.
// ---------------------------------------------------------------------------
template<int MODE>
__global__ __launch_bounds__(256, 2)
void gemm_tf32(const float* __restrict__ A, const float* __restrict__ W,
               float* __restrict__ C, int M, int N, int K, int H, float scale)
{
    constexpr int BM = 128, BN = 128, BK = 32, STAGES = 3;
    constexpr int LDA = BK + 4;   // 36
    constexpr int LDB = BN + 4;   // 132
    constexpr int ASZ = BM * LDA; // 4608 floats
    constexpr int BSZ = BK * LDB; // 4224 floats
    extern __shared__ float smg[];
    float* As = smg;                   // STAGES * ASZ
    float* Bs = smg + STAGES * ASZ;    // STAGES * BSZ

    const int tid  = threadIdx.x;
    const int lane = tid & 31;
    const int wid  = tid >> 5;
    const int g    = lane >> 2;       // 0..7
    const int tg   = lane & 3;        // 0..3
    const int m0 = blockIdx.y * BM;
    const int n0 = blockIdx.x * BN;
    const int wm = (wid >> 1) * 32;   // 4 m-warps
    const int wn = (wid & 1) * 64;    // 2 n-warps

    const uint32_t sA = (uint32_t)__cvta_generic_to_shared(As);
    const uint32_t sB = (uint32_t)__cvta_generic_to_shared(Bs);

    float acc[2][8][4];
    #pragma unroll
    for (int i = 0; i < 2; i++)
        #pragma unroll
        for (int j = 0; j < 8; j++)
            #pragma unroll
            for (int r = 0; r < 4; r++) acc[i][j][r] = 0.0f;

    auto load_stage = [&](int s, int k0) {
        uint32_t ab = sA + (uint32_t)(s * ASZ) * 4u;
        uint32_t bb = sB + (uint32_t)(s * BSZ) * 4u;
        #pragma unroll
        for (int it = 0; it < 4; ++it) {
            int e = tid + it * 256;              // A: 128x32 -> 1024 float4
            int r = e >> 3, c = (e & 7) << 2;
            cp_async16(ab + (uint32_t)(r * LDA + c) * 4u, A + (size_t)(m0 + r) * K + k0 + c);
        }
        #pragma unroll
        for (int it = 0; it < 4; ++it) {
            int e = tid + it * 256;              // B: 32x128
            int r = e >> 5, c = (e & 31) << 2;
            cp_async16(bb + (uint32_t)(r * LDB + c) * 4u, W + (size_t)(k0 + r) * N + n0 + c);
        }
        cp_async_commit();
    };

    const int nIter = K / BK;
    load_stage(0, 0);
    load_stage(1, BK);

    for (int it = 0; it < nIter; ++it) {
        cp_async_wait1();
        __syncthreads();

        const float* Ab = As + (it % STAGES) * ASZ;
        const float* Bb = Bs + (it % STAGES) * BSZ;

        #pragma unroll
        for (int kk = 0; kk < 4; ++kk) {
            uint32_t af[2][4];
            #pragma unroll
            for (int mt = 0; mt < 2; ++mt) {
                const float* ap = Ab + (size_t)(wm + mt * 16) * LDA + kk * 8;
                af[mt][0] = f2tf(ap[(size_t)(g    ) * LDA + tg    ]);
                af[mt][1] = f2tf(ap[(size_t)(g + 8) * LDA + tg    ]);
                af[mt][2] = f2tf(ap[(size_t)(g    ) * LDA + tg + 4]);
                af[mt][3] = f2tf(ap[(size_t)(g + 8) * LDA + tg + 4]);
            }
            #pragma unroll
            for (int nt = 0; nt < 8; ++nt) {
                // B(k, n): thread (g, tg) holds B(tg, g) and B(tg+4, g)
                const float* bp = Bb + (size_t)(kk * 8 + tg) * LDB + wn + nt * 8 + g;
                uint32_t b0 = f2tf(bp[0]);
                uint32_t b1 = f2tf(bp[4 * LDB]);
                mma_tf32(acc[0][nt], af[0], b0, b1);
                mma_tf32(acc[1][nt], af[1], b0, b1);
            }
        }

        int nld = it + STAGES - 1;
        if (nld < nIter) load_stage(nld % STAGES, nld * BK);
    }

    // Direct epilogue: float2 stores (32B sector aligned per 4-lane group)
    #pragma unroll
    for (int mt = 0; mt < 2; ++mt) {
        int r0 = m0 + wm + mt * 16 + g;
        #pragma unroll
        for (int nt = 0; nt < 8; ++nt) {
            int c = n0 + wn + nt * 8 + 2 * tg;
            float2 v0 = make_float2(acc[mt][nt][0], acc[mt][nt][1]);
            float2 v1 = make_float2(acc[mt][nt][2], acc[mt][nt][3]);
            if (MODE == 0) {
                *reinterpret_cast<float2*>(C + (size_t)r0 * N + c)       = v0;
                *reinterpret_cast<float2*>(C + (size_t)(r0 + 8) * N + c) = v1;
            } else {
                int hh = c >> 7, dd = c & (DH - 1);
                {
                    int bb = r0 >> 11, ss = r0 & (Sn - 1);
                    float2 t; t.x = v0.x * scale; t.y = v0.y * scale;
                    *reinterpret_cast<float2*>(C + (((size_t)bb * H + hh) * Sn + ss) * DH + dd) = t;
                }
                {
                    int r1 = r0 + 8;
                    int bb = r1 >> 11, ss = r1 & (Sn - 1);
                    float2 t; t.x = v1.x * scale; t.y = v1.y * scale;
                    *reinterpret_cast<float2*>(C + (((size_t)bb * H + hh) * Sn + ss) * DH + dd) = t;
                }
            }
        }
    }
}

// ---------------------------------------------------------------------------
// Flash attention: 128 q-rows/CTA, 64-key tiles, mma.sync m16n8k8 tf32.
// Q, O in registers; raw fp32 K/V double-buffered via cp.async; cvt.rna at
// operand load (no smem conversion pass). Heavy q-blocks launch first.
// Grid: (S/128, NH, B). 256 threads.
// ---------------------------------------------------------------------------
#define LDK 132

__global__ __launch_bounds__(256, 1)
void attn2(const float* __restrict__ qh, const float* __restrict__ kh,
           const float* __restrict__ vh, float* __restrict__ z)
{
    extern __shared__ float sm[];   // 2 bufs x (K 64x132 + V 64x132)
    const int tid  = threadIdx.x;
    const int lane = tid & 31;
    const int w    = tid >> 5;
    const int g    = lane >> 2;
    const int tg   = lane & 3;

    const int qblk = (int)gridDim.x - 1 - (int)blockIdx.x;  // heavy blocks first
    const int h    = blockIdx.y;
    const int b    = blockIdx.z;
    const int hk   = h >> 2;
    const int q0   = qblk * 128;

    const float* Qg = qh + (((size_t)b * NH  + h ) * Sn + q0) * DH;
    const float* Kg = kh + ((size_t)b * NKV + hk) * Sn * DH;
    const float* Vg = vh + ((size_t)b * NKV + hk) * Sn * DH;

    const uint32_t smbase = (uint32_t)__cvta_generic_to_shared(sm);
    constexpr int BUFF = 2 * 64 * LDK;

    auto load_kv_async = [&](int bsel, int kt) {
        uint32_t base = smbase + (uint32_t)(bsel * BUFF) * 4u;
        const float* Kt = Kg + (size_t)kt * 64 * DH;
        const float* Vt = Vg + (size_t)kt * 64 * DH;
        #pragma unroll
        for (int it = 0; it < 8; ++it) {
            int e = tid + it * 256;
            int r = e >> 5, c = (e & 31) << 2;
            cp_async16(base + (uint32_t)(r * LDK + c) * 4u,            Kt + (size_t)r * DH + c);
            cp_async16(base + (uint32_t)(64 * LDK + r * LDK + c) * 4u, Vt + (size_t)r * DH + c);
        }
        cp_async_commit();
    };

    load_kv_async(0, 0);

    // Q fragments (one-time strided LDG + cvt.rna) — overlaps with first cp.async
    uint32_t Qa[16][4];
    {
        const float* qw = Qg + (size_t)(w * 16) * DH;
        #pragma unroll
        for (int ks = 0; ks < 16; ++ks) {
            Qa[ks][0] = f2tf(qw[(size_t)(g    ) * DH + ks * 8 + tg    ]);
            Qa[ks][1] = f2tf(qw[(size_t)(g + 8) * DH + ks * 8 + tg    ]);
            Qa[ks][2] = f2tf(qw[(size_t)(g    ) * DH + ks * 8 + tg + 4]);
            Qa[ks][3] = f2tf(qw[(size_t)(g + 8) * DH + ks * 8 + tg + 4]);
        }
    }

    float O[16][4];
    #pragma unroll
    for (int nv = 0; nv < 16; ++nv)
        #pragma unroll
        for (int i = 0; i < 4; ++i) O[nv][i] = 0.0f;
    float m0 = -1e30f, m1 = -1e30f, l0 = 0.0f, l1 = 0.0f;

    const int ktmax = 2 * qblk + 1;

    cp_async_wait0();
    __syncthreads();

    int buf = 0;
    for (int kt = 0; kt <= ktmax; ++kt) {
        const float* Ks = sm + buf * BUFF;
        const float* Vs = Ks + 64 * LDK;

        if (kt < ktmax) load_kv_async(buf ^ 1, kt + 1);

        // ---- S = Q K^T : per warp 16x64, 8 n-tiles (cvt.rna on K operands) ----
        float S[8][4];
        #pragma unroll
        for (int n = 0; n < 8; ++n)
            #pragma unroll
            for (int i = 0; i < 4; ++i) S[n][i] = 0.0f;

        #pragma unroll
        for (int ks = 0; ks < 16; ++ks) {
            #pragma unroll
            for (int n = 0; n < 8; ++n) {
                const float* kp = Ks + (size_t)(n * 8 + g) * LDK + ks * 8 + tg;
                uint32_t b0 = f2tf(kp[0]);
                uint32_t b1 = f2tf(kp[4]);
                mma_tf32(S[n], Qa[ks], b0, b1);
            }
        }

        // ---- causal mask + online softmax (registers) ----
        const int grow0 = q0 + w * 16 + g;
        const int grow1 = grow0 + 8;
        const int kb = kt * 64;
        float mx0 = -1e30f, mx1 = -1e30f;
        #pragma unroll
        for (int n = 0; n < 8; ++n) {
            int c = kb + n * 8 + 2 * tg;
            if (c     > grow0) S[n][0] = -1e30f;
            if (c + 1 > grow0) S[n][1] = -1e30f;
            if (c     > grow1) S[n][2] = -1e30f;
            if (c + 1 > grow1) S[n][3] = -1e30f;
            mx0 = fmaxf(mx0, fmaxf(S[n][0], S[n][1]));
            mx1 = fmaxf(mx1, fmaxf(S[n][2], S[n][3]));
        }
        mx0 = fmaxf(mx0, __shfl_xor_sync(0xffffffffu, mx0, 1));
        mx0 = fmaxf(mx0, __shfl_xor_sync(0xffffffffu, mx0, 2));
        mx1 = fmaxf(mx1, __shfl_xor_sync(0xffffffffu, mx1, 1));
        mx1 = fmaxf(mx1, __shfl_xor_sync(0xffffffffu, mx1, 2));

        float mn0 = fmaxf(m0, mx0), mn1 = fmaxf(m1, mx1);
        float al0 = __expf(m0 - mn0), al1 = __expf(m1 - mn1);
        m0 = mn0; m1 = mn1;

        float s0 = 0.0f, s1 = 0.0f;
        #pragma unroll
        for (int n = 0; n < 8; ++n) {
            S[n][0] = __expf(S[n][0] - mn0); s0 += S[n][0];
            S[n][1] = __expf(S[n][1] - mn0); s0 += S[n][1];
            S[n][2] = __expf(S[n][2] - mn1); s1 += S[n][2];
            S[n][3] = __expf(S[n][3] - mn1); s1 += S[n][3];
        }
        s0 += __shfl_xor_sync(0xffffffffu, s0, 1);
        s0 += __shfl_xor_sync(0xffffffffu, s0, 2);
        s1 += __shfl_xor_sync(0xffffffffu, s1, 1);
        s1 += __shfl_xor_sync(0xffffffffu, s1, 2);
        l0 = l0 * al0 + s0;
        l1 = l1 * al1 + s1;

        #pragma unroll
        for (int nv = 0; nv < 16; ++nv) {
            O[nv][0] *= al0; O[nv][1] *= al0;
            O[nv][2] *= al1; O[nv][3] *= al1;
        }

        // ---- O += P V : P relayout via shuffles; cvt.rna on V operands ----
        #pragma unroll
        for (int ks = 0; ks < 8; ++ks) {
            int srcA = (lane & ~3) | (tg >> 1);
            int srcB = srcA + 2;
            float x0 = __shfl_sync(0xffffffffu, S[ks][0], srcA);
            float x1 = __shfl_sync(0xffffffffu, S[ks][1], srcA);
            float x2 = __shfl_sync(0xffffffffu, S[ks][2], srcA);
            float x3 = __shfl_sync(0xffffffffu, S[ks][3], srcA);
            float y0 = __shfl_sync(0xffffffffu, S[ks][0], srcB);
            float y1 = __shfl_sync(0xffffffffu, S[ks][1], srcB);
            float y2 = __shfl_sync(0xffffffffu, S[ks][2], srcB);
            float y3 = __shfl_sync(0xffffffffu, S[ks][3], srcB);
            bool odd = (tg & 1) != 0;
            uint32_t a[4];
            a[0] = f2tf(odd ? x1 : x0);
            a[1] = f2tf(odd ? x3 : x2);
            a[2] = f2tf(odd ? y1 : y0);
            a[3] = f2tf(odd ? y3 : y2);
            #pragma unroll
            for (int nv = 0; nv < 16; ++nv) {
                uint32_t b0 = f2tf(Vs[(size_t)(ks * 8 + tg    ) * LDK + nv * 8 + g]);
                uint32_t b1 = f2tf(Vs[(size_t)(ks * 8 + tg + 4) * LDK + nv * 8 + g]);
                mma_tf32(O[nv], a, b0, b1);
            }
        }

        cp_async_wait0();
        __syncthreads();
        buf ^= 1;
    }

    // ---- normalize and write Z[b, s, h*DH + d] ----
    float inv0 = 1.0f / l0;
    float inv1 = 1.0f / l1;
    float* zp = z + ((size_t)b * Sn + q0 + w * 16) * (NH * DH) + h * DH;
    #pragma unroll
    for (int nv = 0; nv < 16; ++nv) {
        int c = nv * 8 + 2 * tg;
        float2 v0; v0.x = O[nv][0] * inv0; v0.y = O[nv][1] * inv0;
        float2 v1; v1.x = O[nv][2] * inv1; v1.y = O[nv][3] * inv1;
        *reinterpret_cast<float2*>(zp + (size_t)(g    ) * (NH * DH) + c) = v0;
        *reinterpret_cast<float2*>(zp + (size_t)(g + 8) * (NH * DH) + c) = v1;
    }
}

// ---------------------------------------------------------------------------
extern "C" void kernel_launch(void* const* d_in, const int* in_sizes, int n_in,
                              void* d_out, int out_size)
{
    const float* q  = (const float*)d_in[0];
    const float* k  = (const float*)d_in[1];
    const float* v  = (const float*)d_in[2];
    const float* Wq = (const float*)d_in[3];
    const float* Wk = (const float*)d_in[4];
    const float* Wv = (const float*)d_in[5];
    const float* Wo = (const float*)d_in[6];
    float* out = (float*)d_out;

    float *qh, *khp, *vhp, *zbuf;
    cudaGetSymbolAddress((void**)&qh,  g_qh);
    cudaGetSymbolAddress((void**)&khp, g_kh);
    cudaGetSymbolAddress((void**)&vhp, g_vh);
    cudaGetSymbolAddress((void**)&zbuf, g_z);

    const float scale = 0.29730177875068026f;  // 128^-0.25 (applied to Q and K)

    const int smemGemm = 3 * (128 * 36 + 32 * 132) * (int)sizeof(float);  // 105984
    cudaFuncSetAttribute(gemm_tf32<0>, cudaFuncAttributeMaxDynamicSharedMemorySize, smemGemm);
    cudaFuncSetAttribute(gemm_tf32<1>, cudaFuncAttributeMaxDynamicSharedMemorySize, smemGemm);
    const int smemAttn = 2 * 2 * 64 * LDK * (int)sizeof(float);  // 135168
    cudaFuncSetAttribute(attn2, cudaFuncAttributeMaxDynamicSharedMemorySize, smemAttn);

    dim3 blk(256);
    gemm_tf32<1><<<dim3(EMB / 128,      MROWS / 128), blk, smemGemm>>>(q, Wq, qh,  MROWS, EMB,      EMB, NH,  scale);
    gemm_tf32<1><<<dim3((NKV*DH) / 128, MROWS / 128), blk, smemGemm>>>(k, Wk, khp, MROWS, NKV * DH, EMB, NKV, scale);
    gemm_tf32<1><<<dim3((NKV*DH) / 128, MROWS / 128), blk, smemGemm>>>(v, Wv, vhp, MROWS, NKV * DH, EMB, NKV, 1.0f);

    attn2<<<dim3(Sn / 128, NH, Bn), blk, smemAttn>>>(qh, khp, vhp, zbuf);

    gemm_tf32<0><<<dim3(EMB / 128, MROWS / 128), blk, smemGemm>>>(zbuf, Wo, out, MROWS, EMB, EMB, 0, 1.0f);
}

// round 6
// speedup vs baseline: 5.6388x; 2.3326x over previous
#include <cuda_runtime.h>
#include <cuda_fp16.h>
#include <cstdint>

// Problem constants
#define Bn   2
#define Sn   2048
#define EMB  2048
#define NH   16
#define NKV  4
#define DH   128
#define MROWS (Bn*Sn)   // 4096

// fp16 scratch (device globals; no runtime allocation allowed)
__device__ __half g_hq [(size_t)MROWS*EMB];      // fp16 copies of inputs
__device__ __half g_hk [(size_t)MROWS*EMB];
__device__ __half g_hv [(size_t)MROWS*EMB];
__device__ __half g_hWq[(size_t)EMB*EMB];        // scale folded
__device__ __half g_hWk[(size_t)EMB*NKV*DH];     // scale folded
__device__ __half g_hWv[(size_t)EMB*NKV*DH];
__device__ __half g_hWo[(size_t)EMB*EMB];
__device__ __half g_qh [(size_t)Bn*NH*Sn*DH];    // [B,H,S,D]
__device__ __half g_kh [(size_t)Bn*NKV*Sn*DH];
__device__ __half g_vh [(size_t)Bn*NKV*Sn*DH];
__device__ __half g_z  [(size_t)Bn*Sn*NH*DH];    // [B,S,H*D]

__device__ __forceinline__ void mma_f16(float c[4], const uint32_t a[4], uint32_t b0, uint32_t b1) {
    asm volatile("mma.sync.aligned.m16n8k16.row.col.f32.f16.f16.f32 "
        "{%0,%1,%2,%3},{%4,%5,%6,%7},{%8,%9},{%0,%1,%2,%3};"
        : "+f"(c[0]), "+f"(c[1]), "+f"(c[2]), "+f"(c[3])
        : "r"(a[0]), "r"(a[1]), "r"(a[2]), "r"(a[3]), "r"(b0), "r"(b1));
}
__device__ __forceinline__ void ldmx4(uint32_t& r0, uint32_t& r1, uint32_t& r2, uint32_t& r3, uint32_t addr) {
    asm volatile("ldmatrix.sync.aligned.m8n8.x4.shared.b16 {%0,%1,%2,%3}, [%4];"
        : "=r"(r0), "=r"(r1), "=r"(r2), "=r"(r3) : "r"(addr));
}
__device__ __forceinline__ void ldmx4t(uint32_t& r0, uint32_t& r1, uint32_t& r2, uint32_t& r3, uint32_t addr) {
    asm volatile("ldmatrix.sync.aligned.m8n8.x4.trans.shared.b16 {%0,%1,%2,%3}, [%4];"
        : "=r"(r0), "=r"(r1), "=r"(r2), "=r"(r3) : "r"(addr));
}
__device__ __forceinline__ uint32_t packh2(float lo, float hi) {
    uint32_t r;
    asm("cvt.rn.f16x2.f32 %0, %1, %2;" : "=r"(r) : "f"(hi), "f"(lo));
    return r;
}
__device__ __forceinline__ void cp_async16(uint32_t saddr, const void* gptr) {
    asm volatile("cp.async.ca.shared.global [%0], [%1], 16;\n"
        :: "r"(saddr), "l"(__cvta_generic_to_global(gptr)));
}
__device__ __forceinline__ void cp_async_commit() { asm volatile("cp.async.commit_group;\n"); }
__device__ __forceinline__ void cp_async_wait0()  { asm volatile("cp.async.wait_group 0;\n"); }
__device__ __forceinline__ void cp_async_wait2()  { asm volatile("cp.async.wait_group 2;\n"); }

// ---------------------------------------------------------------------------
// fp32 -> fp16 convert (with optional scale), float4-vectorized
// ---------------------------------------------------------------------------
__global__ void cvt16(const float* __restrict__ in, __half* __restrict__ out, int n4, float s)
{
    int i = blockIdx.x * blockDim.x + threadIdx.x;
    if (i >= n4) return;
    float4 v = reinterpret_cast<const float4*>(in)[i];
    __half2 h0 = __floats2half2_rn(v.x * s, v.y * s);
    __half2 h1 = __floats2half2_rn(v.z * s, v.w * s);
    uint2 u; u.x = *reinterpret_cast<uint32_t*>(&h0); u.y = *reinterpret_cast<uint32_t*>(&h1);
    reinterpret_cast<uint2*>(out)[i] = u;
}

// ---------------------------------------------------------------------------
// fp16 GEMM: C = A[M,K] @ W[K,N], fp32 accum. 4-stage cp.async pipeline,
// ldmatrix operands, m16n8k16 HMMA. 8 warps = 4(m) x 2(n); warp tile 32x64.
// Every iteration commits exactly one group (empty in the tail) so that
// wait_group 2 always proves stage `it` has landed — no tail race.
// MODE 0: fp32 row-major output; MODE 1: fp16 scatter to [B,H,S,D].
// ---------------------------------------------------------------------------
template<int MODE>
__global__ __launch_bounds__(256, 2)
void gemm_f16(const __half* __restrict__ A, const __half* __restrict__ W,
              void* __restrict__ Cv, int M, int N, int K, int H)
{
    constexpr int BM = 128, BN = 128, BK = 32, STAGES = 4;
    constexpr int LDA = 40;            // halves (80B rows)
    constexpr int LDB = 136;           // halves (272B rows)
    constexpr int ASZ = BM * LDA;
    constexpr int BSZ = BK * LDB;
    extern __shared__ __half smh[];
    __half* As = smh;
    __half* Bs = smh + STAGES * ASZ;

    const int tid  = threadIdx.x;
    const int lane = tid & 31;
    const int wid  = tid >> 5;
    const int g    = lane >> 2;
    const int tg   = lane & 3;
    const int m0 = blockIdx.y * BM;
    const int n0 = blockIdx.x * BN;
    const int wm = (wid >> 1) * 32;    // 4 m-warps
    const int wn = (wid & 1) * 64;     // 2 n-warps

    const uint32_t sA = (uint32_t)__cvta_generic_to_shared(As);
    const uint32_t sB = (uint32_t)__cvta_generic_to_shared(Bs);

    float acc[2][8][4];
    #pragma unroll
    for (int i = 0; i < 2; i++)
        #pragma unroll
        for (int j = 0; j < 8; j++)
            #pragma unroll
            for (int r = 0; r < 4; r++) acc[i][j][r] = 0.0f;

    auto load_stage = [&](int s, int k0) {
        uint32_t ab = sA + (uint32_t)(s * ASZ) * 2u;
        uint32_t bb = sB + (uint32_t)(s * BSZ) * 2u;
        #pragma unroll
        for (int it = 0; it < 2; ++it) {           // A: 128x32 halves = 512 16B chunks
            int e = tid + it * 256;
            int r = e >> 2, c = (e & 3) * 8;
            cp_async16(ab + (uint32_t)(r * LDA + c) * 2u, A + (size_t)(m0 + r) * K + k0 + c);
        }
        #pragma unroll
        for (int it = 0; it < 2; ++it) {           // B: 32x128 halves = 512 chunks
            int e = tid + it * 256;
            int r = e >> 4, c = (e & 15) * 8;
            cp_async16(bb + (uint32_t)(r * LDB + c) * 2u, W + (size_t)(k0 + r) * N + n0 + c);
        }
        cp_async_commit();
    };

    const int nIter = K / BK;
    load_stage(0, 0);
    load_stage(1, BK);
    load_stage(2, 2 * BK);

    const int lrow = lane & 15;
    const int lcol = (lane >> 4) * 8;

    for (int it = 0; it < nIter; ++it) {
        cp_async_wait2();
        __syncthreads();

        const int s = it % STAGES;
        const uint32_t Ab = sA + (uint32_t)(s * ASZ) * 2u;
        const uint32_t Bb = sB + (uint32_t)(s * BSZ) * 2u;

        #pragma unroll
        for (int kk = 0; kk < 2; ++kk) {           // two k16 steps
            uint32_t af[2][4];
            #pragma unroll
            for (int mt = 0; mt < 2; ++mt)
                ldmx4(af[mt][0], af[mt][1], af[mt][2], af[mt][3],
                      Ab + (uint32_t)((wm + mt * 16 + lrow) * LDA + kk * 16 + lcol) * 2u);
            uint32_t bf[16];
            #pragma unroll
            for (int p = 0; p < 4; ++p)
                ldmx4t(bf[p * 4 + 0], bf[p * 4 + 1], bf[p * 4 + 2], bf[p * 4 + 3],
                       Bb + (uint32_t)((kk * 16 + lrow) * LDB + wn + p * 16 + lcol) * 2u);
            #pragma unroll
            for (int nt = 0; nt < 8; ++nt) {
                uint32_t b0 = bf[(nt >> 1) * 4 + (nt & 1) * 2    ];
                uint32_t b1 = bf[(nt >> 1) * 4 + (nt & 1) * 2 + 1];
                mma_f16(acc[0][nt], af[0], b0, b1);
                mma_f16(acc[1][nt], af[1], b0, b1);
            }
        }

        int nld = it + STAGES - 1;
        if (nld < nIter) load_stage(nld % STAGES, nld * BK);
        else             cp_async_commit();        // empty group: keeps wait_group 2 sound in tail
    }

    // Epilogue
    #pragma unroll
    for (int mt = 0; mt < 2; ++mt) {
        int r0 = m0 + wm + mt * 16 + g;
        #pragma unroll
        for (int nt = 0; nt < 8; ++nt) {
            int c = n0 + wn + nt * 8 + 2 * tg;
            if (MODE == 0) {
                float* C = (float*)Cv;
                *reinterpret_cast<float2*>(C + (size_t)r0 * N + c) =
                    make_float2(acc[mt][nt][0], acc[mt][nt][1]);
                *reinterpret_cast<float2*>(C + (size_t)(r0 + 8) * N + c) =
                    make_float2(acc[mt][nt][2], acc[mt][nt][3]);
            } else {
                __half* C = (__half*)Cv;
                int hh = c >> 7, dd = c & (DH - 1);
                {
                    int bb = r0 >> 11, ss = r0 & (Sn - 1);
                    __half2 t = __floats2half2_rn(acc[mt][nt][0], acc[mt][nt][1]);
                    *reinterpret_cast<__half2*>(C + (((size_t)bb * H + hh) * Sn + ss) * DH + dd) = t;
                }
                {
                    int r1 = r0 + 8;
                    int bb = r1 >> 11, ss = r1 & (Sn - 1);
                    __half2 t = __floats2half2_rn(acc[mt][nt][2], acc[mt][nt][3]);
                    *reinterpret_cast<__half2*>(C + (((size_t)bb * H + hh) * Sn + ss) * DH + dd) = t;
                }
            }
        }
    }
}

// ---------------------------------------------------------------------------
// Flash attention (fp16 operands, fp32 accum): 128 q-rows/CTA, 64-key tiles.
// m16n8k16 HMMA; K/V via cp.async fp16 double-buffer + ldmatrix; P relayout is
// the C-frag->A-frag identity (cvt.rn.f16x2 only). Grid: (S/128, NH, B).
// Uses wait_group 0 per iteration — tail-safe by construction.
// ---------------------------------------------------------------------------
#define LDKH 136   // halves per K/V smem row (272B)

__global__ __launch_bounds__(256, 1)
void attn3(const __half* __restrict__ qh, const __half* __restrict__ kh,
           const __half* __restrict__ vh, __half* __restrict__ z)
{
    extern __shared__ __half smh[];   // 2 bufs x (K 64x136 + V 64x136)
    const int tid  = threadIdx.x;
    const int lane = tid & 31;
    const int w    = tid >> 5;
    const int g    = lane >> 2;
    const int tg   = lane & 3;
    const int lrow = lane & 15;
    const int lcol = (lane >> 4) * 8;

    const int qblk = (int)gridDim.x - 1 - (int)blockIdx.x;  // heavy blocks first
    const int h    = blockIdx.y;
    const int b    = blockIdx.z;
    const int hk   = h >> 2;
    const int q0   = qblk * 128;

    const __half* Qg = qh + (((size_t)b * NH  + h ) * Sn + q0) * DH;
    const __half* Kg = kh + ((size_t)b * NKV + hk) * Sn * DH;
    const __half* Vg = vh + ((size_t)b * NKV + hk) * Sn * DH;

    const uint32_t smbase = (uint32_t)__cvta_generic_to_shared(smh);
    constexpr int BUFF = 2 * 64 * LDKH;   // halves per buffer (K+V)

    auto load_kv_async = [&](int bsel, int kt) {
        uint32_t base = smbase + (uint32_t)(bsel * BUFF) * 2u;
        const __half* Kt = Kg + (size_t)kt * 64 * DH;
        const __half* Vt = Vg + (size_t)kt * 64 * DH;
        #pragma unroll
        for (int it = 0; it < 4; ++it) {          // 64x128 halves = 1024 chunks
            int e = tid + it * 256;
            int r = e >> 4, c = (e & 15) * 8;
            cp_async16(base + (uint32_t)(r * LDKH + c) * 2u,             Kt + (size_t)r * DH + c);
            cp_async16(base + (uint32_t)((64 + r) * LDKH + c) * 2u,      Vt + (size_t)r * DH + c);
        }
        cp_async_commit();
    };

    load_kv_async(0, 0);

    // Q fragments: 8 k16-steps x 4 b32 (half2), loaded once from global
    uint32_t Qa[8][4];
    {
        const __half* qw = Qg + (size_t)(w * 16) * DH;
        #pragma unroll
        for (int ks = 0; ks < 8; ++ks) {
            Qa[ks][0] = *reinterpret_cast<const uint32_t*>(qw + (size_t)(g    ) * DH + ks * 16 + 2 * tg);
            Qa[ks][1] = *reinterpret_cast<const uint32_t*>(qw + (size_t)(g + 8) * DH + ks * 16 + 2 * tg);
            Qa[ks][2] = *reinterpret_cast<const uint32_t*>(qw + (size_t)(g    ) * DH + ks * 16 + 8 + 2 * tg);
            Qa[ks][3] = *reinterpret_cast<const uint32_t*>(qw + (size_t)(g + 8) * DH + ks * 16 + 8 + 2 * tg);
        }
    }

    float O[16][4];
    #pragma unroll
    for (int nv = 0; nv < 16; ++nv)
        #pragma unroll
        for (int i = 0; i < 4; ++i) O[nv][i] = 0.0f;
    float m0 = -1e30f, m1 = -1e30f, l0 = 0.0f, l1 = 0.0f;

    const int ktmax = 2 * qblk + 1;

    cp_async_wait0();
    __syncthreads();

    int buf = 0;
    for (int kt = 0; kt <= ktmax; ++kt) {
        const uint32_t Ksb = smbase + (uint32_t)(buf * BUFF) * 2u;
        const uint32_t Vsb = Ksb + (uint32_t)(64 * LDKH) * 2u;

        if (kt < ktmax) load_kv_async(buf ^ 1, kt + 1);

        // ---- S = Q K^T : 16x64 per warp; K b-frags via ldmatrix (non-trans) ----
        float S[8][4];
        #pragma unroll
        for (int n = 0; n < 8; ++n)
            #pragma unroll
            for (int i = 0; i < 4; ++i) S[n][i] = 0.0f;

        #pragma unroll
        for (int kd = 0; kd < 8; ++kd) {          // 8 k16-steps over DH
            uint32_t bf[16];
            #pragma unroll
            for (int p = 0; p < 4; ++p)           // j rows in 4 chunks of 16
                ldmx4(bf[p * 4 + 0], bf[p * 4 + 1], bf[p * 4 + 2], bf[p * 4 + 3],
                      Ksb + (uint32_t)((p * 16 + lrow) * LDKH + kd * 16 + lcol) * 2u);
            #pragma unroll
            for (int n = 0; n < 8; ++n) {
                uint32_t b0 = bf[(n >> 1) * 4 + (n & 1)    ];
                uint32_t b1 = bf[(n >> 1) * 4 + (n & 1) + 2];
                mma_f16(S[n], Qa[kd], b0, b1);
            }
        }

        // ---- causal mask + online softmax (fp32 registers) ----
        const int grow0 = q0 + w * 16 + g;
        const int grow1 = grow0 + 8;
        const int kb = kt * 64;
        float mx0 = -1e30f, mx1 = -1e30f;
        #pragma unroll
        for (int n = 0; n < 8; ++n) {
            int c = kb + n * 8 + 2 * tg;
            if (c     > grow0) S[n][0] = -1e30f;
            if (c + 1 > grow0) S[n][1] = -1e30f;
            if (c     > grow1) S[n][2] = -1e30f;
            if (c + 1 > grow1) S[n][3] = -1e30f;
            mx0 = fmaxf(mx0, fmaxf(S[n][0], S[n][1]));
            mx1 = fmaxf(mx1, fmaxf(S[n][2], S[n][3]));
        }
        mx0 = fmaxf(mx0, __shfl_xor_sync(0xffffffffu, mx0, 1));
        mx0 = fmaxf(mx0, __shfl_xor_sync(0xffffffffu, mx0, 2));
        mx1 = fmaxf(mx1, __shfl_xor_sync(0xffffffffu, mx1, 1));
        mx1 = fmaxf(mx1, __shfl_xor_sync(0xffffffffu, mx1, 2));

        float mn0 = fmaxf(m0, mx0), mn1 = fmaxf(m1, mx1);
        float al0 = __expf(m0 - mn0), al1 = __expf(m1 - mn1);
        m0 = mn0; m1 = mn1;

        float s0 = 0.0f, s1 = 0.0f;
        #pragma unroll
        for (int n = 0; n < 8; ++n) {
            S[n][0] = __expf(S[n][0] - mn0); s0 += S[n][0];
            S[n][1] = __expf(S[n][1] - mn0); s0 += S[n][1];
            S[n][2] = __expf(S[n][2] - mn1); s1 += S[n][2];
            S[n][3] = __expf(S[n][3] - mn1); s1 += S[n][3];
        }
        s0 += __shfl_xor_sync(0xffffffffu, s0, 1);
        s0 += __shfl_xor_sync(0xffffffffu, s0, 2);
        s1 += __shfl_xor_sync(0xffffffffu, s1, 1);
        s1 += __shfl_xor_sync(0xffffffffu, s1, 2);
        l0 = l0 * al0 + s0;
        l1 = l1 * al1 + s1;

        #pragma unroll
        for (int nv = 0; nv < 16; ++nv) {
            O[nv][0] *= al0; O[nv][1] *= al0;
            O[nv][2] *= al1; O[nv][3] *= al1;
        }

        // ---- O += P V : C-frag -> A-frag identity (pack only); V via ldmatrix.trans ----
        #pragma unroll
        for (int ks = 0; ks < 4; ++ks) {          // 4 k16-steps over 64 keys
            uint32_t a[4];
            a[0] = packh2(S[2 * ks    ][0], S[2 * ks    ][1]);
            a[1] = packh2(S[2 * ks    ][2], S[2 * ks    ][3]);
            a[2] = packh2(S[2 * ks + 1][0], S[2 * ks + 1][1]);
            a[3] = packh2(S[2 * ks + 1][2], S[2 * ks + 1][3]);
            #pragma unroll
            for (int p = 0; p < 8; ++p) {         // d in 8 chunks of 16 -> 2 n-tiles each
                uint32_t r0, r1, r2, r3;
                ldmx4t(r0, r1, r2, r3,
                       Vsb + (uint32_t)((ks * 16 + lrow) * LDKH + p * 16 + lcol) * 2u);
                mma_f16(O[2 * p    ], a, r0, r1);
                mma_f16(O[2 * p + 1], a, r2, r3);
            }
        }

        cp_async_wait0();
        __syncthreads();
        buf ^= 1;
    }

    // ---- normalize and write Z[b, s, h*DH + d] (fp16) ----
    float inv0 = 1.0f / l0;
    float inv1 = 1.0f / l1;
    __half* zp = z + ((size_t)b * Sn + q0 + w * 16) * (NH * DH) + h * DH;
    #pragma unroll
    for (int nv = 0; nv < 16; ++nv) {
        int c = nv * 8 + 2 * tg;
        __half2 v0 = __floats2half2_rn(O[nv][0] * inv0, O[nv][1] * inv0);
        __half2 v1 = __floats2half2_rn(O[nv][2] * inv1, O[nv][3] * inv1);
        *reinterpret_cast<__half2*>(zp + (size_t)(g    ) * (NH * DH) + c) = v0;
        *reinterpret_cast<__half2*>(zp + (size_t)(g + 8) * (NH * DH) + c) = v1;
    }
}

// ---------------------------------------------------------------------------
extern "C" void kernel_launch(void* const* d_in, const int* in_sizes, int n_in,
                              void* d_out, int out_size)
{
    const float* q  = (const float*)d_in[0];
    const float* k  = (const float*)d_in[1];
    const float* v  = (const float*)d_in[2];
    const float* Wq = (const float*)d_in[3];
    const float* Wk = (const float*)d_in[4];
    const float* Wv = (const float*)d_in[5];
    const float* Wo = (const float*)d_in[6];
    float* out = (float*)d_out;

    __half *hq, *hk, *hv, *hWq, *hWk, *hWv, *hWo, *qh, *khp, *vhp, *zbuf;
    cudaGetSymbolAddress((void**)&hq,  g_hq);
    cudaGetSymbolAddress((void**)&hk,  g_hk);
    cudaGetSymbolAddress((void**)&hv,  g_hv);
    cudaGetSymbolAddress((void**)&hWq, g_hWq);
    cudaGetSymbolAddress((void**)&hWk, g_hWk);
    cudaGetSymbolAddress((void**)&hWv, g_hWv);
    cudaGetSymbolAddress((void**)&hWo, g_hWo);
    cudaGetSymbolAddress((void**)&qh,  g_qh);
    cudaGetSymbolAddress((void**)&khp, g_kh);
    cudaGetSymbolAddress((void**)&vhp, g_vh);
    cudaGetSymbolAddress((void**)&zbuf, g_z);

    const float scale = 0.29730177875068026f;  // 128^-0.25 (folded into Wq, Wk)

    // fp32 -> fp16 conversions
    {
        const int T = 256;
        int nIn = MROWS * EMB / 4;
        cvt16<<<(nIn + T - 1) / T, T>>>(q, hq, nIn, 1.0f);
        cvt16<<<(nIn + T - 1) / T, T>>>(k, hk, nIn, 1.0f);
        cvt16<<<(nIn + T - 1) / T, T>>>(v, hv, nIn, 1.0f);
        int nWq = EMB * EMB / 4;
        cvt16<<<(nWq + T - 1) / T, T>>>(Wq, hWq, nWq, scale);
        int nWk = EMB * NKV * DH / 4;
        cvt16<<<(nWk + T - 1) / T, T>>>(Wk, hWk, nWk, scale);
        cvt16<<<(nWk + T - 1) / T, T>>>(Wv, hWv, nWk, 1.0f);
        cvt16<<<(nWq + T - 1) / T, T>>>(Wo, hWo, nWq, 1.0f);
    }

    const int smemGemm = 4 * (128 * 40 + 32 * 136) * (int)sizeof(__half);  // 75776
    cudaFuncSetAttribute(gemm_f16<0>, cudaFuncAttributeMaxDynamicSharedMemorySize, smemGemm);
    cudaFuncSetAttribute(gemm_f16<1>, cudaFuncAttributeMaxDynamicSharedMemorySize, smemGemm);
    const int smemAttn = 2 * 2 * 64 * LDKH * (int)sizeof(__half);          // 69632
    cudaFuncSetAttribute(attn3, cudaFuncAttributeMaxDynamicSharedMemorySize, smemAttn);

    dim3 blk(256);
    gemm_f16<1><<<dim3(EMB / 128,      MROWS / 128), blk, smemGemm>>>(hq, hWq, qh,  MROWS, EMB,      EMB, NH);
    gemm_f16<1><<<dim3((NKV*DH) / 128, MROWS / 128), blk, smemGemm>>>(hk, hWk, khp, MROWS, NKV * DH, EMB, NKV);
    gemm_f16<1><<<dim3((NKV*DH) / 128, MROWS / 128), blk, smemGemm>>>(hv, hWv, vhp, MROWS, NKV * DH, EMB, NKV);

    attn3<<<dim3(Sn / 128, NH, Bn), blk, smemAttn>>>(qh, khp, vhp, zbuf);

    gemm_f16<0><<<dim3(EMB / 128, MROWS / 128), blk, smemGemm>>>(zbuf, hWo, out, MROWS, EMB, EMB, 0);
}

// round 7
// speedup vs baseline: 5.8730x; 1.0415x over previous
#include <cuda_runtime.h>
#include <cuda_fp16.h>
#include <cstdint>

// Problem constants
#define Bn   2
#define Sn   2048
#define EMB  2048
#define NH   16
#define NKV  4
#define DH   128
#define MROWS (Bn*Sn)   // 4096

// fp16 scratch (device globals; no runtime allocation allowed)
__device__ __half g_hq [(size_t)MROWS*EMB];
__device__ __half g_hk [(size_t)MROWS*EMB];
__device__ __half g_hv [(size_t)MROWS*EMB];
__device__ __half g_hWq[(size_t)EMB*EMB];        // scale folded
__device__ __half g_hWk[(size_t)EMB*NKV*DH];     // scale folded
__device__ __half g_hWv[(size_t)EMB*NKV*DH];
__device__ __half g_hWo[(size_t)EMB*EMB];
__device__ __half g_qh [(size_t)Bn*NH*Sn*DH];    // [B,H,S,D]
__device__ __half g_kh [(size_t)Bn*NKV*Sn*DH];
__device__ __half g_vh [(size_t)Bn*NKV*Sn*DH];
__device__ __half g_z  [(size_t)Bn*Sn*NH*DH];    // [B,S,H*D]

__device__ __forceinline__ void mma_f16(float c[4], const uint32_t a[4], uint32_t b0, uint32_t b1) {
    asm volatile("mma.sync.aligned.m16n8k16.row.col.f32.f16.f16.f32 "
        "{%0,%1,%2,%3},{%4,%5,%6,%7},{%8,%9},{%0,%1,%2,%3};"
        : "+f"(c[0]), "+f"(c[1]), "+f"(c[2]), "+f"(c[3])
        : "r"(a[0]), "r"(a[1]), "r"(a[2]), "r"(a[3]), "r"(b0), "r"(b1));
}
__device__ __forceinline__ void ldmx4(uint32_t& r0, uint32_t& r1, uint32_t& r2, uint32_t& r3, uint32_t addr) {
    asm volatile("ldmatrix.sync.aligned.m8n8.x4.shared.b16 {%0,%1,%2,%3}, [%4];"
        : "=r"(r0), "=r"(r1), "=r"(r2), "=r"(r3) : "r"(addr));
}
__device__ __forceinline__ void ldmx4t(uint32_t& r0, uint32_t& r1, uint32_t& r2, uint32_t& r3, uint32_t addr) {
    asm volatile("ldmatrix.sync.aligned.m8n8.x4.trans.shared.b16 {%0,%1,%2,%3}, [%4];"
        : "=r"(r0), "=r"(r1), "=r"(r2), "=r"(r3) : "r"(addr));
}
__device__ __forceinline__ uint32_t packh2(float lo, float hi) {
    uint32_t r;
    asm("cvt.rn.f16x2.f32 %0, %1, %2;" : "=r"(r) : "f"(hi), "f"(lo));
    return r;
}
__device__ __forceinline__ void cp_async16(uint32_t saddr, const void* gptr) {
    asm volatile("cp.async.ca.shared.global [%0], [%1], 16;\n"
        :: "r"(saddr), "l"(__cvta_generic_to_global(gptr)));
}
__device__ __forceinline__ void cp_async_commit() { asm volatile("cp.async.commit_group;\n"); }
__device__ __forceinline__ void cp_async_wait0()  { asm volatile("cp.async.wait_group 0;\n"); }
__device__ __forceinline__ void cp_async_wait1()  { asm volatile("cp.async.wait_group 1;\n"); }
__device__ __forceinline__ void cp_async_wait2()  { asm volatile("cp.async.wait_group 2;\n"); }

// ---------------------------------------------------------------------------
// Fused fp32 -> fp16 convert for all 7 tensors, one launch.
// ---------------------------------------------------------------------------
#define NQ4  ((long)MROWS*EMB/4)          // 2097152 per input tensor
#define WQ4  ((long)EMB*EMB/4)            // 1048576
#define WK4  ((long)EMB*NKV*DH/4)         // 262144
#define CVT_TOTAL (3*NQ4 + 2*WQ4 + 2*WK4) // 8912896

__global__ __launch_bounds__(256)
void cvt_all(const float4* __restrict__ q, const float4* __restrict__ k, const float4* __restrict__ v,
             const float4* __restrict__ Wq, const float4* __restrict__ Wk,
             const float4* __restrict__ Wv, const float4* __restrict__ Wo,
             uint2* hq, uint2* hk, uint2* hv, uint2* hWq, uint2* hWk, uint2* hWv, uint2* hWo,
             float scale)
{
    long i = (long)blockIdx.x * blockDim.x + threadIdx.x;
    if (i >= CVT_TOTAL) return;
    const float4* src; uint2* dst; long off; float s = 1.0f;
    if      (i <     NQ4)             { src = q;  dst = hq;  off = i; }
    else if (i < 2 * NQ4)             { src = k;  dst = hk;  off = i - NQ4; }
    else if (i < 3 * NQ4)             { src = v;  dst = hv;  off = i - 2 * NQ4; }
    else if (i < 3 * NQ4 + WQ4)       { src = Wq; dst = hWq; off = i - 3 * NQ4; s = scale; }
    else if (i < 3 * NQ4 + WQ4 + WK4) { src = Wk; dst = hWk; off = i - 3 * NQ4 - WQ4; s = scale; }
    else if (i < 3 * NQ4 + WQ4 + 2 * WK4) { src = Wv; dst = hWv; off = i - 3 * NQ4 - WQ4 - WK4; }
    else                              { src = Wo; dst = hWo; off = i - 3 * NQ4 - WQ4 - 2 * WK4; }
    float4 x = src[off];
    __half2 h0 = __floats2half2_rn(x.x * s, x.y * s);
    __half2 h1 = __floats2half2_rn(x.z * s, x.w * s);
    uint2 u; u.x = *reinterpret_cast<uint32_t*>(&h0); u.y = *reinterpret_cast<uint32_t*>(&h1);
    dst[off] = u;
}

// ---------------------------------------------------------------------------
// Shared GEMM mainloop body (device function): C[128x128 tile] = A @ W,
// fp16 in, fp32 accum. 4-stage cp.async, loads issued at top (3 in flight),
// empty-commit in tail keeps wait_group 2 sound.
// ---------------------------------------------------------------------------
struct GemmCore {
    static constexpr int BM = 128, BN = 128, BK = 32, STAGES = 4;
    static constexpr int LDA = 40, LDB = 136;
    static constexpr int ASZ = BM * LDA, BSZ = BK * LDB;
};

template<typename F>
__device__ __forceinline__ void gemm_mainloop(
    const __half* __restrict__ A, const __half* __restrict__ W,
    int M, int N, int K, int m0, int n0,
    int tid, int wid, int lane, float acc[2][8][4], __half* smh, F&&)
{
    using GC = GemmCore;
    __half* As = smh;
    __half* Bs = smh + GC::STAGES * GC::ASZ;
    const uint32_t sA = (uint32_t)__cvta_generic_to_shared(As);
    const uint32_t sB = (uint32_t)__cvta_generic_to_shared(Bs);
    const int wm = (wid >> 1) * 32;
    const int wn = (wid & 1) * 64;
    const int lrow = lane & 15;
    const int lcol = (lane >> 4) * 8;

    auto load_stage = [&](int s, int k0) {
        uint32_t ab = sA + (uint32_t)(s * GC::ASZ) * 2u;
        uint32_t bb = sB + (uint32_t)(s * GC::BSZ) * 2u;
        #pragma unroll
        for (int it = 0; it < 2; ++it) {
            int e = tid + it * 256;
            int r = e >> 2, c = (e & 3) * 8;
            cp_async16(ab + (uint32_t)(r * GC::LDA + c) * 2u, A + (size_t)(m0 + r) * K + k0 + c);
        }
        #pragma unroll
        for (int it = 0; it < 2; ++it) {
            int e = tid + it * 256;
            int r = e >> 4, c = (e & 15) * 8;
            cp_async16(bb + (uint32_t)(r * GC::LDB + c) * 2u, W + (size_t)(k0 + r) * N + n0 + c);
        }
        cp_async_commit();
    };

    const int nIter = K / GC::BK;
    load_stage(0, 0);
    load_stage(1, GC::BK);
    load_stage(2, 2 * GC::BK);

    for (int it = 0; it < nIter; ++it) {
        cp_async_wait2();
        __syncthreads();

        int nld = it + GC::STAGES - 1;
        if (nld < nIter) load_stage(nld % GC::STAGES, nld * GC::BK);
        else             cp_async_commit();   // empty group: invariant committed = it+3

        const int s = it % GC::STAGES;
        const uint32_t Ab = sA + (uint32_t)(s * GC::ASZ) * 2u;
        const uint32_t Bb = sB + (uint32_t)(s * GC::BSZ) * 2u;

        #pragma unroll
        for (int kk = 0; kk < 2; ++kk) {
            uint32_t af[2][4];
            #pragma unroll
            for (int mt = 0; mt < 2; ++mt)
                ldmx4(af[mt][0], af[mt][1], af[mt][2], af[mt][3],
                      Ab + (uint32_t)((wm + mt * 16 + lrow) * GC::LDA + kk * 16 + lcol) * 2u);
            uint32_t bf[16];
            #pragma unroll
            for (int p = 0; p < 4; ++p)
                ldmx4t(bf[p * 4 + 0], bf[p * 4 + 1], bf[p * 4 + 2], bf[p * 4 + 3],
                       Bb + (uint32_t)((kk * 16 + lrow) * GC::LDB + wn + p * 16 + lcol) * 2u);
            #pragma unroll
            for (int nt = 0; nt < 8; ++nt) {
                uint32_t b0 = bf[(nt >> 1) * 4 + (nt & 1) * 2    ];
                uint32_t b1 = bf[(nt >> 1) * 4 + (nt & 1) * 2 + 1];
                mma_f16(acc[0][nt], af[0], b0, b1);
                mma_f16(acc[1][nt], af[1], b0, b1);
            }
        }
    }
}

// ---------------------------------------------------------------------------
// Fused Q/K/V projection: one launch, blockIdx.x in [0,24):
//   [0,16)  Q proj (N=2048, H=16) -> g_qh
//   [16,20) K proj (N=512,  H=4)  -> g_kh
//   [20,24) V proj (N=512,  H=4)  -> g_vh
// Scatter epilogue to [B,H,S,D] fp16.
// ---------------------------------------------------------------------------
__global__ __launch_bounds__(256, 2)
void proj_qkv(const __half* __restrict__ hq, const __half* __restrict__ hk, const __half* __restrict__ hv,
              const __half* __restrict__ hWq, const __half* __restrict__ hWk, const __half* __restrict__ hWv,
              __half* __restrict__ qh, __half* __restrict__ kh, __half* __restrict__ vh)
{
    extern __shared__ __half smh[];
    const int tid  = threadIdx.x;
    const int lane = tid & 31;
    const int wid  = tid >> 5;
    const int g    = lane >> 2;
    const int tg   = lane & 3;

    const int bx = blockIdx.x;
    const __half *A, *W; __half* C; int N, H, nb;
    if (bx < 16)      { A = hq; W = hWq; C = qh; N = EMB;      H = NH;  nb = bx; }
    else if (bx < 20) { A = hk; W = hWk; C = kh; N = NKV * DH; H = NKV; nb = bx - 16; }
    else              { A = hv; W = hWv; C = vh; N = NKV * DH; H = NKV; nb = bx - 20; }

    const int m0 = blockIdx.y * 128;
    const int n0 = nb * 128;
    const int wm = (wid >> 1) * 32;
    const int wn = (wid & 1) * 64;

    float acc[2][8][4];
    #pragma unroll
    for (int i = 0; i < 2; i++)
        #pragma unroll
        for (int j = 0; j < 8; j++)
            #pragma unroll
            for (int r = 0; r < 4; r++) acc[i][j][r] = 0.0f;

    gemm_mainloop(A, W, MROWS, N, EMB, m0, n0, tid, wid, lane, acc, smh, 0);

    // Scatter epilogue
    #pragma unroll
    for (int mt = 0; mt < 2; ++mt) {
        int r0 = m0 + wm + mt * 16 + g;
        #pragma unroll
        for (int nt = 0; nt < 8; ++nt) {
            int c = n0 + wn + nt * 8 + 2 * tg;
            int hh = c >> 7, dd = c & (DH - 1);
            {
                int bb = r0 >> 11, ss = r0 & (Sn - 1);
                __half2 t = __floats2half2_rn(acc[mt][nt][0], acc[mt][nt][1]);
                *reinterpret_cast<__half2*>(C + (((size_t)bb * H + hh) * Sn + ss) * DH + dd) = t;
            }
            {
                int r1 = r0 + 8;
                int bb = r1 >> 11, ss = r1 & (Sn - 1);
                __half2 t = __floats2half2_rn(acc[mt][nt][2], acc[mt][nt][3]);
                *reinterpret_cast<__half2*>(C + (((size_t)bb * H + hh) * Sn + ss) * DH + dd) = t;
            }
        }
    }
}

// ---------------------------------------------------------------------------
// Output projection: fp32 row-major out.
// ---------------------------------------------------------------------------
__global__ __launch_bounds__(256, 2)
void proj_out(const __half* __restrict__ A, const __half* __restrict__ W,
              float* __restrict__ C, int M, int N, int K)
{
    extern __shared__ __half smh[];
    const int tid  = threadIdx.x;
    const int lane = tid & 31;
    const int wid  = tid >> 5;
    const int g    = lane >> 2;
    const int tg   = lane & 3;
    const int m0 = blockIdx.y * 128;
    const int n0 = blockIdx.x * 128;
    const int wm = (wid >> 1) * 32;
    const int wn = (wid & 1) * 64;

    float acc[2][8][4];
    #pragma unroll
    for (int i = 0; i < 2; i++)
        #pragma unroll
        for (int j = 0; j < 8; j++)
            #pragma unroll
            for (int r = 0; r < 4; r++) acc[i][j][r] = 0.0f;

    gemm_mainloop(A, W, M, N, K, m0, n0, tid, wid, lane, acc, smh, 0);

    #pragma unroll
    for (int mt = 0; mt < 2; ++mt) {
        int r0 = m0 + wm + mt * 16 + g;
        #pragma unroll
        for (int nt = 0; nt < 8; ++nt) {
            int c = n0 + wn + nt * 8 + 2 * tg;
            *reinterpret_cast<float2*>(C + (size_t)r0 * N + c) =
                make_float2(acc[mt][nt][0], acc[mt][nt][1]);
            *reinterpret_cast<float2*>(C + (size_t)(r0 + 8) * N + c) =
                make_float2(acc[mt][nt][2], acc[mt][nt][3]);
        }
    }
}

// ---------------------------------------------------------------------------
// Flash attention (fp16 operands, fp32 accum): 128 q-rows/CTA, 64-key tiles,
// 3-stage K/V cp.async pipeline, loads issued at top of iteration.
// Empty-commit in tail keeps wait_group 1 sound. Grid: (S/128, NH, B).
// ---------------------------------------------------------------------------
#define LDKH 136   // halves per K/V smem row (272B)

__global__ __launch_bounds__(256, 1)
void attn3(const __half* __restrict__ qh, const __half* __restrict__ kh,
           const __half* __restrict__ vh, __half* __restrict__ z)
{
    extern __shared__ __half smh[];   // 3 bufs x (K 64x136 + V 64x136)
    const int tid  = threadIdx.x;
    const int lane = tid & 31;
    const int w    = tid >> 5;
    const int g    = lane >> 2;
    const int tg   = lane & 3;
    const int lrow = lane & 15;
    const int lcol = (lane >> 4) * 8;

    const int qblk = (int)gridDim.x - 1 - (int)blockIdx.x;  // heavy blocks first
    const int h    = blockIdx.y;
    const int b    = blockIdx.z;
    const int hk   = h >> 2;
    const int q0   = qblk * 128;

    const __half* Qg = qh + (((size_t)b * NH  + h ) * Sn + q0) * DH;
    const __half* Kg = kh + ((size_t)b * NKV + hk) * Sn * DH;
    const __half* Vg = vh + ((size_t)b * NKV + hk) * Sn * DH;

    const uint32_t smbase = (uint32_t)__cvta_generic_to_shared(smh);
    constexpr int BUFF = 2 * 64 * LDKH;   // halves per buffer (K+V)

    auto load_kv_async = [&](int bsel, int kt) {
        uint32_t base = smbase + (uint32_t)(bsel * BUFF) * 2u;
        const __half* Kt = Kg + (size_t)kt * 64 * DH;
        const __half* Vt = Vg + (size_t)kt * 64 * DH;
        #pragma unroll
        for (int it = 0; it < 4; ++it) {
            int e = tid + it * 256;
            int r = e >> 4, c = (e & 15) * 8;
            cp_async16(base + (uint32_t)(r * LDKH + c) * 2u,        Kt + (size_t)r * DH + c);
            cp_async16(base + (uint32_t)((64 + r) * LDKH + c) * 2u, Vt + (size_t)r * DH + c);
        }
        cp_async_commit();
    };

    const int ktmax = 2 * qblk + 1;   // >= 1 always

    load_kv_async(0, 0);
    load_kv_async(1, 1);

    // Q fragments: 8 k16-steps x 4 b32 (half2), loaded once from global
    uint32_t Qa[8][4];
    {
        const __half* qw = Qg + (size_t)(w * 16) * DH;
        #pragma unroll
        for (int ks = 0; ks < 8; ++ks) {
            Qa[ks][0] = *reinterpret_cast<const uint32_t*>(qw + (size_t)(g    ) * DH + ks * 16 + 2 * tg);
            Qa[ks][1] = *reinterpret_cast<const uint32_t*>(qw + (size_t)(g + 8) * DH + ks * 16 + 2 * tg);
            Qa[ks][2] = *reinterpret_cast<const uint32_t*>(qw + (size_t)(g    ) * DH + ks * 16 + 8 + 2 * tg);
            Qa[ks][3] = *reinterpret_cast<const uint32_t*>(qw + (size_t)(g + 8) * DH + ks * 16 + 8 + 2 * tg);
        }
    }

    float O[16][4];
    #pragma unroll
    for (int nv = 0; nv < 16; ++nv)
        #pragma unroll
        for (int i = 0; i < 4; ++i) O[nv][i] = 0.0f;
    float m0 = -1e30f, m1 = -1e30f, l0 = 0.0f, l1 = 0.0f;

    for (int kt = 0; kt <= ktmax; ++kt) {
        // tile kt ready when retired >= kt+1 groups; committed == kt+2 (invariant)
        cp_async_wait1();
        __syncthreads();

        int nk = kt + 2;
        if (nk <= ktmax) load_kv_async(nk % 3, nk);
        else             cp_async_commit();   // empty group keeps invariant

        const uint32_t Ksb = smbase + (uint32_t)((kt % 3) * BUFF) * 2u;
        const uint32_t Vsb = Ksb + (uint32_t)(64 * LDKH) * 2u;

        // ---- S = Q K^T ----
        float S[8][4];
        #pragma unroll
        for (int n = 0; n < 8; ++n)
            #pragma unroll
            for (int i = 0; i < 4; ++i) S[n][i] = 0.0f;

        #pragma unroll
        for (int kd = 0; kd < 8; ++kd) {
            uint32_t bf[16];
            #pragma unroll
            for (int p = 0; p < 4; ++p)
                ldmx4(bf[p * 4 + 0], bf[p * 4 + 1], bf[p * 4 + 2], bf[p * 4 + 3],
                      Ksb + (uint32_t)((p * 16 + lrow) * LDKH + kd * 16 + lcol) * 2u);
            #pragma unroll
            for (int n = 0; n < 8; ++n) {
                uint32_t b0 = bf[(n >> 1) * 4 + (n & 1)    ];
                uint32_t b1 = bf[(n >> 1) * 4 + (n & 1) + 2];
                mma_f16(S[n], Qa[kd], b0, b1);
            }
        }

        // ---- causal mask + online softmax ----
        const int grow0 = q0 + w * 16 + g;
        const int grow1 = grow0 + 8;
        const int kb = kt * 64;
        float mx0 = -1e30f, mx1 = -1e30f;
        #pragma unroll
        for (int n = 0; n < 8; ++n) {
            int c = kb + n * 8 + 2 * tg;
            if (c     > grow0) S[n][0] = -1e30f;
            if (c + 1 > grow0) S[n][1] = -1e30f;
            if (c     > grow1) S[n][2] = -1e30f;
            if (c + 1 > grow1) S[n][3] = -1e30f;
            mx0 = fmaxf(mx0, fmaxf(S[n][0], S[n][1]));
            mx1 = fmaxf(mx1, fmaxf(S[n][2], S[n][3]));
        }
        mx0 = fmaxf(mx0, __shfl_xor_sync(0xffffffffu, mx0, 1));
        mx0 = fmaxf(mx0, __shfl_xor_sync(0xffffffffu, mx0, 2));
        mx1 = fmaxf(mx1, __shfl_xor_sync(0xffffffffu, mx1, 1));
        mx1 = fmaxf(mx1, __shfl_xor_sync(0xffffffffu, mx1, 2));

        float mn0 = fmaxf(m0, mx0), mn1 = fmaxf(m1, mx1);
        float al0 = __expf(m0 - mn0), al1 = __expf(m1 - mn1);
        m0 = mn0; m1 = mn1;

        float s0 = 0.0f, s1 = 0.0f;
        #pragma unroll
        for (int n = 0; n < 8; ++n) {
            S[n][0] = __expf(S[n][0] - mn0); s0 += S[n][0];
            S[n][1] = __expf(S[n][1] - mn0); s0 += S[n][1];
            S[n][2] = __expf(S[n][2] - mn1); s1 += S[n][2];
            S[n][3] = __expf(S[n][3] - mn1); s1 += S[n][3];
        }
        s0 += __shfl_xor_sync(0xffffffffu, s0, 1);
        s0 += __shfl_xor_sync(0xffffffffu, s0, 2);
        s1 += __shfl_xor_sync(0xffffffffu, s1, 1);
        s1 += __shfl_xor_sync(0xffffffffu, s1, 2);
        l0 = l0 * al0 + s0;
        l1 = l1 * al1 + s1;

        #pragma unroll
        for (int nv = 0; nv < 16; ++nv) {
            O[nv][0] *= al0; O[nv][1] *= al0;
            O[nv][2] *= al1; O[nv][3] *= al1;
        }

        // ---- O += P V ----
        #pragma unroll
        for (int ks = 0; ks < 4; ++ks) {
            uint32_t a[4];
            a[0] = packh2(S[2 * ks    ][0], S[2 * ks    ][1]);
            a[1] = packh2(S[2 * ks    ][2], S[2 * ks    ][3]);
            a[2] = packh2(S[2 * ks + 1][0], S[2 * ks + 1][1]);
            a[3] = packh2(S[2 * ks + 1][2], S[2 * ks + 1][3]);
            #pragma unroll
            for (int p = 0; p < 8; ++p) {
                uint32_t r0, r1, r2, r3;
                ldmx4t(r0, r1, r2, r3,
                       Vsb + (uint32_t)((ks * 16 + lrow) * LDKH + p * 16 + lcol) * 2u);
                mma_f16(O[2 * p    ], a, r0, r1);
                mma_f16(O[2 * p + 1], a, r2, r3);
            }
        }
    }

    // ---- normalize and write Z (fp16) ----
    float inv0 = 1.0f / l0;
    float inv1 = 1.0f / l1;
    __half* zp = z + ((size_t)b * Sn + q0 + w * 16) * (NH * DH) + h * DH;
    #pragma unroll
    for (int nv = 0; nv < 16; ++nv) {
        int c = nv * 8 + 2 * tg;
        __half2 v0 = __floats2half2_rn(O[nv][0] * inv0, O[nv][1] * inv0);
        __half2 v1 = __floats2half2_rn(O[nv][2] * inv1, O[nv][3] * inv1);
        *reinterpret_cast<__half2*>(zp + (size_t)(g    ) * (NH * DH) + c) = v0;
        *reinterpret_cast<__half2*>(zp + (size_t)(g + 8) * (NH * DH) + c) = v1;
    }
}

// ---------------------------------------------------------------------------
extern "C" void kernel_launch(void* const* d_in, const int* in_sizes, int n_in,
                              void* d_out, int out_size)
{
    const float* q  = (const float*)d_in[0];
    const float* k  = (const float*)d_in[1];
    const float* v  = (const float*)d_in[2];
    const float* Wq = (const float*)d_in[3];
    const float* Wk = (const float*)d_in[4];
    const float* Wv = (const float*)d_in[5];
    const float* Wo = (const float*)d_in[6];
    float* out = (float*)d_out;

    __half *hq, *hk, *hv, *hWq, *hWk, *hWv, *hWo, *qh, *khp, *vhp, *zbuf;
    cudaGetSymbolAddress((void**)&hq,  g_hq);
    cudaGetSymbolAddress((void**)&hk,  g_hk);
    cudaGetSymbolAddress((void**)&hv,  g_hv);
    cudaGetSymbolAddress((void**)&hWq, g_hWq);
    cudaGetSymbolAddress((void**)&hWk, g_hWk);
    cudaGetSymbolAddress((void**)&hWv, g_hWv);
    cudaGetSymbolAddress((void**)&hWo, g_hWo);
    cudaGetSymbolAddress((void**)&qh,  g_qh);
    cudaGetSymbolAddress((void**)&khp, g_kh);
    cudaGetSymbolAddress((void**)&vhp, g_vh);
    cudaGetSymbolAddress((void**)&zbuf, g_z);

    const float scale = 0.29730177875068026f;  // 128^-0.25 (folded into Wq, Wk)

    // One fused convert launch
    {
        long total = CVT_TOTAL;
        int blocks = (int)((total + 255) / 256);
        cvt_all<<<blocks, 256>>>(
            (const float4*)q, (const float4*)k, (const float4*)v,
            (const float4*)Wq, (const float4*)Wk, (const float4*)Wv, (const float4*)Wo,
            (uint2*)hq, (uint2*)hk, (uint2*)hv, (uint2*)hWq, (uint2*)hWk, (uint2*)hWv, (uint2*)hWo,
            scale);
    }

    const int smemGemm = GemmCore::STAGES * (GemmCore::ASZ + GemmCore::BSZ) * (int)sizeof(__half); // 75776
    cudaFuncSetAttribute(proj_qkv, cudaFuncAttributeMaxDynamicSharedMemorySize, smemGemm);
    cudaFuncSetAttribute(proj_out, cudaFuncAttributeMaxDynamicSharedMemorySize, smemGemm);
    const int smemAttn = 3 * 2 * 64 * LDKH * (int)sizeof(__half);  // 104448
    cudaFuncSetAttribute(attn3, cudaFuncAttributeMaxDynamicSharedMemorySize, smemAttn);

    dim3 blk(256);
    // Fused Q/K/V projections: 24 n-blocks x 32 m-blocks = 768 CTAs
    proj_qkv<<<dim3(24, MROWS / 128), blk, smemGemm>>>(hq, hk, hv, hWq, hWk, hWv, qh, khp, vhp);

    attn3<<<dim3(Sn / 128, NH, Bn), blk, smemAttn>>>(qh, khp, vhp, zbuf);

    proj_out<<<dim3(EMB / 128, MROWS / 128), blk, smemGemm>>>(zbuf, hWo, out, MROWS, EMB, EMB);
}

// round 8
// speedup vs baseline: 6.7876x; 1.1557x over previous
#include <cuda_runtime.h>
#include <cuda_fp16.h>
#include <cstdint>

// Problem constants
#define Bn   2
#define Sn   2048
#define EMB  2048
#define NH   16
#define NKV  4
#define DH   128
#define MROWS (Bn*Sn)   // 4096

// fp16 scratch (device globals; no runtime allocation allowed)
__device__ __half g_hq [(size_t)MROWS*EMB];
__device__ __half g_hk [(size_t)MROWS*EMB];
__device__ __half g_hv [(size_t)MROWS*EMB];
__device__ __half g_hWq[(size_t)EMB*EMB];        // scale folded
__device__ __half g_hWk[(size_t)EMB*NKV*DH];     // scale folded
__device__ __half g_hWv[(size_t)EMB*NKV*DH];
__device__ __half g_hWo[(size_t)EMB*EMB];
__device__ __half g_qh [(size_t)Bn*NH*Sn*DH];    // [B,H,S,D]
__device__ __half g_kh [(size_t)Bn*NKV*Sn*DH];
__device__ __half g_vh [(size_t)Bn*NKV*Sn*DH];
__device__ __half g_z  [(size_t)Bn*Sn*NH*DH];    // [B,S,H*D]

__device__ __forceinline__ void mma_f16(float c[4], const uint32_t a[4], uint32_t b0, uint32_t b1) {
    asm volatile("mma.sync.aligned.m16n8k16.row.col.f32.f16.f16.f32 "
        "{%0,%1,%2,%3},{%4,%5,%6,%7},{%8,%9},{%0,%1,%2,%3};"
        : "+f"(c[0]), "+f"(c[1]), "+f"(c[2]), "+f"(c[3])
        : "r"(a[0]), "r"(a[1]), "r"(a[2]), "r"(a[3]), "r"(b0), "r"(b1));
}
__device__ __forceinline__ void ldmx4(uint32_t& r0, uint32_t& r1, uint32_t& r2, uint32_t& r3, uint32_t addr) {
    asm volatile("ldmatrix.sync.aligned.m8n8.x4.shared.b16 {%0,%1,%2,%3}, [%4];"
        : "=r"(r0), "=r"(r1), "=r"(r2), "=r"(r3) : "r"(addr));
}
__device__ __forceinline__ void ldmx4t(uint32_t& r0, uint32_t& r1, uint32_t& r2, uint32_t& r3, uint32_t addr) {
    asm volatile("ldmatrix.sync.aligned.m8n8.x4.trans.shared.b16 {%0,%1,%2,%3}, [%4];"
        : "=r"(r0), "=r"(r1), "=r"(r2), "=r"(r3) : "r"(addr));
}
__device__ __forceinline__ uint32_t packh2(float lo, float hi) {
    uint32_t r;
    asm("cvt.rn.f16x2.f32 %0, %1, %2;" : "=r"(r) : "f"(hi), "f"(lo));
    return r;
}
__device__ __forceinline__ void cp_async16(uint32_t saddr, const void* gptr) {
    asm volatile("cp.async.ca.shared.global [%0], [%1], 16;\n"
        :: "r"(saddr), "l"(__cvta_generic_to_global(gptr)));
}
__device__ __forceinline__ void cp_async_commit() { asm volatile("cp.async.commit_group;\n"); }
__device__ __forceinline__ void cp_async_wait1()  { asm volatile("cp.async.wait_group 1;\n"); }
__device__ __forceinline__ void cp_async_wait2()  { asm volatile("cp.async.wait_group 2;\n"); }

// ---------------------------------------------------------------------------
// Fused fp32 -> fp16 convert for all 7 tensors, one launch.
// ---------------------------------------------------------------------------
#define NQ4  ((long)MROWS*EMB/4)
#define WQ4  ((long)EMB*EMB/4)
#define WK4  ((long)EMB*NKV*DH/4)
#define CVT_TOTAL (3*NQ4 + 2*WQ4 + 2*WK4)

__global__ __launch_bounds__(256)
void cvt_all(const float4* __restrict__ q, const float4* __restrict__ k, const float4* __restrict__ v,
             const float4* __restrict__ Wq, const float4* __restrict__ Wk,
             const float4* __restrict__ Wv, const float4* __restrict__ Wo,
             uint2* hq, uint2* hk, uint2* hv, uint2* hWq, uint2* hWk, uint2* hWv, uint2* hWo,
             float scale)
{
    long i = (long)blockIdx.x * blockDim.x + threadIdx.x;
    if (i >= CVT_TOTAL) return;
    const float4* src; uint2* dst; long off; float s = 1.0f;
    if      (i <     NQ4)             { src = q;  dst = hq;  off = i; }
    else if (i < 2 * NQ4)             { src = k;  dst = hk;  off = i - NQ4; }
    else if (i < 3 * NQ4)             { src = v;  dst = hv;  off = i - 2 * NQ4; }
    else if (i < 3 * NQ4 + WQ4)       { src = Wq; dst = hWq; off = i - 3 * NQ4; s = scale; }
    else if (i < 3 * NQ4 + WQ4 + WK4) { src = Wk; dst = hWk; off = i - 3 * NQ4 - WQ4; s = scale; }
    else if (i < 3 * NQ4 + WQ4 + 2 * WK4) { src = Wv; dst = hWv; off = i - 3 * NQ4 - WQ4 - WK4; }
    else                              { src = Wo; dst = hWo; off = i - 3 * NQ4 - WQ4 - 2 * WK4; }
    float4 x = src[off];
    __half2 h0 = __floats2half2_rn(x.x * s, x.y * s);
    __half2 h1 = __floats2half2_rn(x.z * s, x.w * s);
    uint2 u; u.x = *reinterpret_cast<uint32_t*>(&h0); u.y = *reinterpret_cast<uint32_t*>(&h1);
    dst[off] = u;
}

// ---------------------------------------------------------------------------
// GEMM core v2: 128 threads (4 warps, 2x2), warp tile 64x64.
// Per k16: 4 A-ldmx4 + 4 B-ldmx4t feed 32 HMMA (0.25 ldm/mma).
// BM=BN=128, BK=32, 4-stage cp.async; empty-commit tail keeps wait_group 2 sound.
// ---------------------------------------------------------------------------
struct GemmCore {
    static constexpr int BM = 128, BN = 128, BK = 32, STAGES = 4, NT = 128;
    static constexpr int LDA = 40, LDB = 136;
    static constexpr int ASZ = BM * LDA, BSZ = BK * LDB;
};

__device__ __forceinline__ void gemm_mainloop(
    const __half* __restrict__ A, const __half* __restrict__ W,
    int N, int K, int m0, int n0,
    int tid, int wid, int lane, float acc[4][8][4], __half* smh)
{
    using GC = GemmCore;
    const uint32_t sA = (uint32_t)__cvta_generic_to_shared(smh);
    const uint32_t sB = sA + (uint32_t)(GC::STAGES * GC::ASZ) * 2u;
    const int wm = (wid >> 1) * 64;
    const int wn = (wid & 1) * 64;
    const int lrow = lane & 15;
    const int lcol = (lane >> 4) * 8;

    auto load_stage = [&](int s, int k0) {
        uint32_t ab = sA + (uint32_t)(s * GC::ASZ) * 2u;
        uint32_t bb = sB + (uint32_t)(s * GC::BSZ) * 2u;
        #pragma unroll
        for (int it = 0; it < 4; ++it) {           // A: 128x32 halves = 512 chunks
            int e = tid + it * GC::NT;
            int r = e >> 2, c = (e & 3) * 8;
            cp_async16(ab + (uint32_t)(r * GC::LDA + c) * 2u, A + (size_t)(m0 + r) * K + k0 + c);
        }
        #pragma unroll
        for (int it = 0; it < 4; ++it) {           // B: 32x128 halves = 512 chunks
            int e = tid + it * GC::NT;
            int r = e >> 4, c = (e & 15) * 8;
            cp_async16(bb + (uint32_t)(r * GC::LDB + c) * 2u, W + (size_t)(k0 + r) * N + n0 + c);
        }
        cp_async_commit();
    };

    const int nIter = K / GC::BK;
    load_stage(0, 0);
    load_stage(1, GC::BK);
    load_stage(2, 2 * GC::BK);

    for (int it = 0; it < nIter; ++it) {
        cp_async_wait2();
        __syncthreads();

        int nld = it + GC::STAGES - 1;
        if (nld < nIter) load_stage(nld % GC::STAGES, nld * GC::BK);
        else             cp_async_commit();   // keep committed = it+3 invariant

        const int s = it % GC::STAGES;
        const uint32_t Ab = sA + (uint32_t)(s * GC::ASZ) * 2u;
        const uint32_t Bb = sB + (uint32_t)(s * GC::BSZ) * 2u;

        #pragma unroll
        for (int kk = 0; kk < 2; ++kk) {
            uint32_t af[4][4];
            #pragma unroll
            for (int mt = 0; mt < 4; ++mt)
                ldmx4(af[mt][0], af[mt][1], af[mt][2], af[mt][3],
                      Ab + (uint32_t)((wm + mt * 16 + lrow) * GC::LDA + kk * 16 + lcol) * 2u);
            uint32_t bf[16];
            #pragma unroll
            for (int p = 0; p < 4; ++p)
                ldmx4t(bf[p * 4 + 0], bf[p * 4 + 1], bf[p * 4 + 2], bf[p * 4 + 3],
                       Bb + (uint32_t)((kk * 16 + lrow) * GC::LDB + wn + p * 16 + lcol) * 2u);
            #pragma unroll
            for (int nt = 0; nt < 8; ++nt) {
                uint32_t b0 = bf[(nt >> 1) * 4 + (nt & 1) * 2    ];
                uint32_t b1 = bf[(nt >> 1) * 4 + (nt & 1) * 2 + 1];
                #pragma unroll
                for (int mt = 0; mt < 4; ++mt)
                    mma_f16(acc[mt][nt], af[mt], b0, b1);
            }
        }
    }
}

// ---------------------------------------------------------------------------
// Fused Q/K/V projection: blockIdx.x in [0,24): Q 16 / K 4 / V 4 n-blocks.
// ---------------------------------------------------------------------------
__global__ __launch_bounds__(128, 2)
void proj_qkv(const __half* __restrict__ hq, const __half* __restrict__ hk, const __half* __restrict__ hv,
              const __half* __restrict__ hWq, const __half* __restrict__ hWk, const __half* __restrict__ hWv,
              __half* __restrict__ qh, __half* __restrict__ kh, __half* __restrict__ vh)
{
    extern __shared__ __half smh[];
    const int tid  = threadIdx.x;
    const int lane = tid & 31;
    const int wid  = tid >> 5;
    const int g    = lane >> 2;
    const int tg   = lane & 3;

    const int bx = blockIdx.x;
    const __half *A, *W; __half* C; int N, H, nb;
    if (bx < 16)      { A = hq; W = hWq; C = qh; N = EMB;      H = NH;  nb = bx; }
    else if (bx < 20) { A = hk; W = hWk; C = kh; N = NKV * DH; H = NKV; nb = bx - 16; }
    else              { A = hv; W = hWv; C = vh; N = NKV * DH; H = NKV; nb = bx - 20; }

    const int m0 = blockIdx.y * 128;
    const int n0 = nb * 128;
    const int wm = (wid >> 1) * 64;
    const int wn = (wid & 1) * 64;

    float acc[4][8][4];
    #pragma unroll
    for (int i = 0; i < 4; i++)
        #pragma unroll
        for (int j = 0; j < 8; j++)
            #pragma unroll
            for (int r = 0; r < 4; r++) acc[i][j][r] = 0.0f;

    gemm_mainloop(A, W, N, EMB, m0, n0, tid, wid, lane, acc, smh);

    #pragma unroll
    for (int mt = 0; mt < 4; ++mt) {
        int r0 = m0 + wm + mt * 16 + g;
        #pragma unroll
        for (int nt = 0; nt < 8; ++nt) {
            int c = n0 + wn + nt * 8 + 2 * tg;
            int hh = c >> 7, dd = c & (DH - 1);
            {
                int bb = r0 >> 11, ss = r0 & (Sn - 1);
                __half2 t = __floats2half2_rn(acc[mt][nt][0], acc[mt][nt][1]);
                *reinterpret_cast<__half2*>(C + (((size_t)bb * H + hh) * Sn + ss) * DH + dd) = t;
            }
            {
                int r1 = r0 + 8;
                int bb = r1 >> 11, ss = r1 & (Sn - 1);
                __half2 t = __floats2half2_rn(acc[mt][nt][2], acc[mt][nt][3]);
                *reinterpret_cast<__half2*>(C + (((size_t)bb * H + hh) * Sn + ss) * DH + dd) = t;
            }
        }
    }
}

// ---------------------------------------------------------------------------
// Output projection: fp32 row-major out.
// ---------------------------------------------------------------------------
__global__ __launch_bounds__(128, 2)
void proj_out(const __half* __restrict__ A, const __half* __restrict__ W,
              float* __restrict__ C, int M, int N, int K)
{
    extern __shared__ __half smh[];
    const int tid  = threadIdx.x;
    const int lane = tid & 31;
    const int wid  = tid >> 5;
    const int g    = lane >> 2;
    const int tg   = lane & 3;
    const int m0 = blockIdx.y * 128;
    const int n0 = blockIdx.x * 128;
    const int wm = (wid >> 1) * 64;
    const int wn = (wid & 1) * 64;

    float acc[4][8][4];
    #pragma unroll
    for (int i = 0; i < 4; i++)
        #pragma unroll
        for (int j = 0; j < 8; j++)
            #pragma unroll
            for (int r = 0; r < 4; r++) acc[i][j][r] = 0.0f;

    gemm_mainloop(A, W, N, K, m0, n0, tid, wid, lane, acc, smh);

    #pragma unroll
    for (int mt = 0; mt < 4; ++mt) {
        int r0 = m0 + wm + mt * 16 + g;
        #pragma unroll
        for (int nt = 0; nt < 8; ++nt) {
            int c = n0 + wn + nt * 8 + 2 * tg;
            *reinterpret_cast<float2*>(C + (size_t)r0 * N + c) =
                make_float2(acc[mt][nt][0], acc[mt][nt][1]);
            *reinterpret_cast<float2*>(C + (size_t)(r0 + 8) * N + c) =
                make_float2(acc[mt][nt][2], acc[mt][nt][3]);
        }
    }
}

// ---------------------------------------------------------------------------
// Flash attention (fp16 operands, fp32 accum): 128 q-rows/CTA, 64-key tiles,
// 3-stage K/V cp.async pipeline, loads issued at top. Grid: (S/128, NH, B).
// ---------------------------------------------------------------------------
#define LDKH 136   // halves per K/V smem row (272B)

__global__ __launch_bounds__(256, 1)
void attn3(const __half* __restrict__ qh, const __half* __restrict__ kh,
           const __half* __restrict__ vh, __half* __restrict__ z)
{
    extern __shared__ __half smh[];   // 3 bufs x (K 64x136 + V 64x136)
    const int tid  = threadIdx.x;
    const int lane = tid & 31;
    const int w    = tid >> 5;
    const int g    = lane >> 2;
    const int tg   = lane & 3;
    const int lrow = lane & 15;
    const int lcol = (lane >> 4) * 8;

    const int qblk = (int)gridDim.x - 1 - (int)blockIdx.x;  // heavy blocks first
    const int h    = blockIdx.y;
    const int b    = blockIdx.z;
    const int hk   = h >> 2;
    const int q0   = qblk * 128;

    const __half* Qg = qh + (((size_t)b * NH  + h ) * Sn + q0) * DH;
    const __half* Kg = kh + ((size_t)b * NKV + hk) * Sn * DH;
    const __half* Vg = vh + ((size_t)b * NKV + hk) * Sn * DH;

    const uint32_t smbase = (uint32_t)__cvta_generic_to_shared(smh);
    constexpr int BUFF = 2 * 64 * LDKH;

    auto load_kv_async = [&](int bsel, int kt) {
        uint32_t base = smbase + (uint32_t)(bsel * BUFF) * 2u;
        const __half* Kt = Kg + (size_t)kt * 64 * DH;
        const __half* Vt = Vg + (size_t)kt * 64 * DH;
        #pragma unroll
        for (int it = 0; it < 4; ++it) {
            int e = tid + it * 256;
            int r = e >> 4, c = (e & 15) * 8;
            cp_async16(base + (uint32_t)(r * LDKH + c) * 2u,        Kt + (size_t)r * DH + c);
            cp_async16(base + (uint32_t)((64 + r) * LDKH + c) * 2u, Vt + (size_t)r * DH + c);
        }
        cp_async_commit();
    };

    const int ktmax = 2 * qblk + 1;

    load_kv_async(0, 0);
    load_kv_async(1, 1);

    uint32_t Qa[8][4];
    {
        const __half* qw = Qg + (size_t)(w * 16) * DH;
        #pragma unroll
        for (int ks = 0; ks < 8; ++ks) {
            Qa[ks][0] = *reinterpret_cast<const uint32_t*>(qw + (size_t)(g    ) * DH + ks * 16 + 2 * tg);
            Qa[ks][1] = *reinterpret_cast<const uint32_t*>(qw + (size_t)(g + 8) * DH + ks * 16 + 2 * tg);
            Qa[ks][2] = *reinterpret_cast<const uint32_t*>(qw + (size_t)(g    ) * DH + ks * 16 + 8 + 2 * tg);
            Qa[ks][3] = *reinterpret_cast<const uint32_t*>(qw + (size_t)(g + 8) * DH + ks * 16 + 8 + 2 * tg);
        }
    }

    float O[16][4];
    #pragma unroll
    for (int nv = 0; nv < 16; ++nv)
        #pragma unroll
        for (int i = 0; i < 4; ++i) O[nv][i] = 0.0f;
    float m0 = -1e30f, m1 = -1e30f, l0 = 0.0f, l1 = 0.0f;

    for (int kt = 0; kt <= ktmax; ++kt) {
        cp_async_wait1();
        __syncthreads();

        int nk = kt + 2;
        if (nk <= ktmax) load_kv_async(nk % 3, nk);
        else             cp_async_commit();

        const uint32_t Ksb = smbase + (uint32_t)((kt % 3) * BUFF) * 2u;
        const uint32_t Vsb = Ksb + (uint32_t)(64 * LDKH) * 2u;

        // ---- S = Q K^T ----
        float S[8][4];
        #pragma unroll
        for (int n = 0; n < 8; ++n)
            #pragma unroll
            for (int i = 0; i < 4; ++i) S[n][i] = 0.0f;

        #pragma unroll
        for (int kd = 0; kd < 8; ++kd) {
            uint32_t bf[16];
            #pragma unroll
            for (int p = 0; p < 4; ++p)
                ldmx4(bf[p * 4 + 0], bf[p * 4 + 1], bf[p * 4 + 2], bf[p * 4 + 3],
                      Ksb + (uint32_t)((p * 16 + lrow) * LDKH + kd * 16 + lcol) * 2u);
            #pragma unroll
            for (int n = 0; n < 8; ++n) {
                uint32_t b0 = bf[(n >> 1) * 4 + (n & 1)    ];
                uint32_t b1 = bf[(n >> 1) * 4 + (n & 1) + 2];
                mma_f16(S[n], Qa[kd], b0, b1);
            }
        }

        // ---- causal mask + online softmax ----
        const int grow0 = q0 + w * 16 + g;
        const int grow1 = grow0 + 8;
        const int kb = kt * 64;
        float mx0 = -1e30f, mx1 = -1e30f;
        #pragma unroll
        for (int n = 0; n < 8; ++n) {
            int c = kb + n * 8 + 2 * tg;
            if (c     > grow0) S[n][0] = -1e30f;
            if (c + 1 > grow0) S[n][1] = -1e30f;
            if (c     > grow1) S[n][2] = -1e30f;
            if (c + 1 > grow1) S[n][3] = -1e30f;
            mx0 = fmaxf(mx0, fmaxf(S[n][0], S[n][1]));
            mx1 = fmaxf(mx1, fmaxf(S[n][2], S[n][3]));
        }
        mx0 = fmaxf(mx0, __shfl_xor_sync(0xffffffffu, mx0, 1));
        mx0 = fmaxf(mx0, __shfl_xor_sync(0xffffffffu, mx0, 2));
        mx1 = fmaxf(mx1, __shfl_xor_sync(0xffffffffu, mx1, 1));
        mx1 = fmaxf(mx1, __shfl_xor_sync(0xffffffffu, mx1, 2));

        float mn0 = fmaxf(m0, mx0), mn1 = fmaxf(m1, mx1);
        float al0 = __expf(m0 - mn0), al1 = __expf(m1 - mn1);
        m0 = mn0; m1 = mn1;

        float s0 = 0.0f, s1 = 0.0f;
        #pragma unroll
        for (int n = 0; n < 8; ++n) {
            S[n][0] = __expf(S[n][0] - mn0); s0 += S[n][0];
            S[n][1] = __expf(S[n][1] - mn0); s0 += S[n][1];
            S[n][2] = __expf(S[n][2] - mn1); s1 += S[n][2];
            S[n][3] = __expf(S[n][3] - mn1); s1 += S[n][3];
        }
        s0 += __shfl_xor_sync(0xffffffffu, s0, 1);
        s0 += __shfl_xor_sync(0xffffffffu, s0, 2);
        s1 += __shfl_xor_sync(0xffffffffu, s1, 1);
        s1 += __shfl_xor_sync(0xffffffffu, s1, 2);
        l0 = l0 * al0 + s0;
        l1 = l1 * al1 + s1;

        #pragma unroll
        for (int nv = 0; nv < 16; ++nv) {
            O[nv][0] *= al0; O[nv][1] *= al0;
            O[nv][2] *= al1; O[nv][3] *= al1;
        }

        // ---- O += P V ----
        #pragma unroll
        for (int ks = 0; ks < 4; ++ks) {
            uint32_t a[4];
            a[0] = packh2(S[2 * ks    ][0], S[2 * ks    ][1]);
            a[1] = packh2(S[2 * ks    ][2], S[2 * ks    ][3]);
            a[2] = packh2(S[2 * ks + 1][0], S[2 * ks + 1][1]);
            a[3] = packh2(S[2 * ks + 1][2], S[2 * ks + 1][3]);
            #pragma unroll
            for (int p = 0; p < 8; ++p) {
                uint32_t r0, r1, r2, r3;
                ldmx4t(r0, r1, r2, r3,
                       Vsb + (uint32_t)((ks * 16 + lrow) * LDKH + p * 16 + lcol) * 2u);
                mma_f16(O[2 * p    ], a, r0, r1);
                mma_f16(O[2 * p + 1], a, r2, r3);
            }
        }
    }

    // ---- normalize and write Z (fp16) ----
    float inv0 = 1.0f / l0;
    float inv1 = 1.0f / l1;
    __half* zp = z + ((size_t)b * Sn + q0 + w * 16) * (NH * DH) + h * DH;
    #pragma unroll
    for (int nv = 0; nv < 16; ++nv) {
        int c = nv * 8 + 2 * tg;
        __half2 v0 = __floats2half2_rn(O[nv][0] * inv0, O[nv][1] * inv0);
        __half2 v1 = __floats2half2_rn(O[nv][2] * inv1, O[nv][3] * inv1);
        *reinterpret_cast<__half2*>(zp + (size_t)(g    ) * (NH * DH) + c) = v0;
        *reinterpret_cast<__half2*>(zp + (size_t)(g + 8) * (NH * DH) + c) = v1;
    }
}

// ---------------------------------------------------------------------------
extern "C" void kernel_launch(void* const* d_in, const int* in_sizes, int n_in,
                              void* d_out, int out_size)
{
    const float* q  = (const float*)d_in[0];
    const float* k  = (const float*)d_in[1];
    const float* v  = (const float*)d_in[2];
    const float* Wq = (const float*)d_in[3];
    const float* Wk = (const float*)d_in[4];
    const float* Wv = (const float*)d_in[5];
    const float* Wo = (const float*)d_in[6];
    float* out = (float*)d_out;

    __half *hq, *hk, *hv, *hWq, *hWk, *hWv, *hWo, *qh, *khp, *vhp, *zbuf;
    cudaGetSymbolAddress((void**)&hq,  g_hq);
    cudaGetSymbolAddress((void**)&hk,  g_hk);
    cudaGetSymbolAddress((void**)&hv,  g_hv);
    cudaGetSymbolAddress((void**)&hWq, g_hWq);
    cudaGetSymbolAddress((void**)&hWk, g_hWk);
    cudaGetSymbolAddress((void**)&hWv, g_hWv);
    cudaGetSymbolAddress((void**)&hWo, g_hWo);
    cudaGetSymbolAddress((void**)&qh,  g_qh);
    cudaGetSymbolAddress((void**)&khp, g_kh);
    cudaGetSymbolAddress((void**)&vhp, g_vh);
    cudaGetSymbolAddress((void**)&zbuf, g_z);

    const float scale = 0.29730177875068026f;  // 128^-0.25 (folded into Wq, Wk)

    {
        long total = CVT_TOTAL;
        int blocks = (int)((total + 255) / 256);
        cvt_all<<<blocks, 256>>>(
            (const float4*)q, (const float4*)k, (const float4*)v,
            (const float4*)Wq, (const float4*)Wk, (const float4*)Wv, (const float4*)Wo,
            (uint2*)hq, (uint2*)hk, (uint2*)hv, (uint2*)hWq, (uint2*)hWk, (uint2*)hWv, (uint2*)hWo,
            scale);
    }

    const int smemGemm = GemmCore::STAGES * (GemmCore::ASZ + GemmCore::BSZ) * (int)sizeof(__half); // 75776
    cudaFuncSetAttribute(proj_qkv, cudaFuncAttributeMaxDynamicSharedMemorySize, smemGemm);
    cudaFuncSetAttribute(proj_out, cudaFuncAttributeMaxDynamicSharedMemorySize, smemGemm);
    const int smemAttn = 3 * 2 * 64 * LDKH * (int)sizeof(__half);  // 104448
    cudaFuncSetAttribute(attn3, cudaFuncAttributeMaxDynamicSharedMemorySize, smemAttn);

    // Fused Q/K/V projections: 24 n-blocks x 32 m-blocks, 128 threads/CTA
    proj_qkv<<<dim3(24, MROWS / 128), 128, smemGemm>>>(hq, hk, hv, hWq, hWk, hWv, qh, khp, vhp);

    attn3<<<dim3(Sn / 128, NH, Bn), 256, smemAttn>>>(qh, khp, vhp, zbuf);

    proj_out<<<dim3(EMB / 128, MROWS / 128), 128, smemGemm>>>(zbuf, hWo, out, MROWS, EMB, EMB);
}

// round 10
// speedup vs baseline: 6.9276x; 1.0206x over previous
#include <cuda_runtime.h>
#include <cuda_fp16.h>
#include <cstdint>

// Problem constants
#define Bn   2
#define Sn   2048
#define EMB  2048
#define NH   16
#define NKV  4
#define DH   128
#define MROWS (Bn*Sn)   // 4096

// fp16 scratch (device globals; no runtime allocation allowed)
__device__ __half g_hq [(size_t)MROWS*EMB];
__device__ __half g_hk [(size_t)MROWS*EMB];
__device__ __half g_hv [(size_t)MROWS*EMB];
__device__ __half g_hWq[(size_t)EMB*EMB];        // scale*log2e folded
__device__ __half g_hWk[(size_t)EMB*NKV*DH];     // scale folded
__device__ __half g_hWv[(size_t)EMB*NKV*DH];
__device__ __half g_hWo[(size_t)EMB*EMB];
__device__ __half g_qh [(size_t)Bn*NH*Sn*DH];    // [B,H,S,D]
__device__ __half g_kh [(size_t)Bn*NKV*Sn*DH];
__device__ __half g_vh [(size_t)Bn*NKV*Sn*DH];
__device__ __half g_z  [(size_t)Bn*Sn*NH*DH];    // [B,S,H*D]

__device__ __forceinline__ void mma_f16(float c[4], const uint32_t a[4], uint32_t b0, uint32_t b1) {
    asm volatile("mma.sync.aligned.m16n8k16.row.col.f32.f16.f16.f32 "
        "{%0,%1,%2,%3},{%4,%5,%6,%7},{%8,%9},{%0,%1,%2,%3};"
        : "+f"(c[0]), "+f"(c[1]), "+f"(c[2]), "+f"(c[3])
        : "r"(a[0]), "r"(a[1]), "r"(a[2]), "r"(a[3]), "r"(b0), "r"(b1));
}
__device__ __forceinline__ void ldmx4(uint32_t& r0, uint32_t& r1, uint32_t& r2, uint32_t& r3, uint32_t addr) {
    asm volatile("ldmatrix.sync.aligned.m8n8.x4.shared.b16 {%0,%1,%2,%3}, [%4];"
        : "=r"(r0), "=r"(r1), "=r"(r2), "=r"(r3) : "r"(addr));
}
__device__ __forceinline__ void ldmx4t(uint32_t& r0, uint32_t& r1, uint32_t& r2, uint32_t& r3, uint32_t addr) {
    asm volatile("ldmatrix.sync.aligned.m8n8.x4.trans.shared.b16 {%0,%1,%2,%3}, [%4];"
        : "=r"(r0), "=r"(r1), "=r"(r2), "=r"(r3) : "r"(addr));
}
__device__ __forceinline__ uint32_t packh2(float lo, float hi) {
    uint32_t r;
    asm("cvt.rn.f16x2.f32 %0, %1, %2;" : "=r"(r) : "f"(hi), "f"(lo));
    return r;
}
__device__ __forceinline__ float ex2f(float x) {
    float r; asm("ex2.approx.ftz.f32 %0, %1;" : "=f"(r) : "f"(x)); return r;
}
__device__ __forceinline__ void cp_async16(uint32_t saddr, const void* gptr) {
    asm volatile("cp.async.ca.shared.global [%0], [%1], 16;\n"
        :: "r"(saddr), "l"(__cvta_generic_to_global(gptr)));
}
__device__ __forceinline__ void cp_async_commit() { asm volatile("cp.async.commit_group;\n"); }
__device__ __forceinline__ void cp_async_wait1()  { asm volatile("cp.async.wait_group 1;\n"); }
__device__ __forceinline__ void cp_async_wait2()  { asm volatile("cp.async.wait_group 2;\n"); }

// ---------------------------------------------------------------------------
// Fused fp32 -> fp16 convert for all 7 tensors, one launch.
// ---------------------------------------------------------------------------
#define NQ4  ((long)MROWS*EMB/4)
#define WQ4  ((long)EMB*EMB/4)
#define WK4  ((long)EMB*NKV*DH/4)
#define CVT_TOTAL (3*NQ4 + 2*WQ4 + 2*WK4)

__global__ __launch_bounds__(256)
void cvt_all(const float4* __restrict__ q, const float4* __restrict__ k, const float4* __restrict__ v,
             const float4* __restrict__ Wq, const float4* __restrict__ Wk,
             const float4* __restrict__ Wv, const float4* __restrict__ Wo,
             uint2* hq, uint2* hk, uint2* hv, uint2* hWq, uint2* hWk, uint2* hWv, uint2* hWo,
             float scaleQ, float scaleK)
{
    long i = (long)blockIdx.x * blockDim.x + threadIdx.x;
    if (i >= CVT_TOTAL) return;
    const float4* src; uint2* dst; long off; float s = 1.0f;
    if      (i <     NQ4)             { src = q;  dst = hq;  off = i; }
    else if (i < 2 * NQ4)             { src = k;  dst = hk;  off = i - NQ4; }
    else if (i < 3 * NQ4)             { src = v;  dst = hv;  off = i - 2 * NQ4; }
    else if (i < 3 * NQ4 + WQ4)       { src = Wq; dst = hWq; off = i - 3 * NQ4; s = scaleQ; }
    else if (i < 3 * NQ4 + WQ4 + WK4) { src = Wk; dst = hWk; off = i - 3 * NQ4 - WQ4; s = scaleK; }
    else if (i < 3 * NQ4 + WQ4 + 2 * WK4) { src = Wv; dst = hWv; off = i - 3 * NQ4 - WQ4 - WK4; }
    else                              { src = Wo; dst = hWo; off = i - 3 * NQ4 - WQ4 - 2 * WK4; }
    float4 x = src[off];
    __half2 h0 = __floats2half2_rn(x.x * s, x.y * s);
    __half2 h1 = __floats2half2_rn(x.z * s, x.w * s);
    uint2 u; u.x = *reinterpret_cast<uint32_t*>(&h0); u.y = *reinterpret_cast<uint32_t*>(&h1);
    dst[off] = u;
}

// ---------------------------------------------------------------------------
// GEMM core: 128 threads (4 warps, 2x2), warp tile 64x64.
// Per k16: 4 A-ldmx4 + 4 B-ldmx4t feed 32 HMMA (0.25 ldm/mma).
// BM=BN=128, BK=32, 4-stage cp.async; empty-commit tail keeps wait_group 2 sound.
// ---------------------------------------------------------------------------
struct GemmCore {
    static constexpr int BM = 128, BN = 128, BK = 32, STAGES = 4, NT = 128;
    static constexpr int LDA = 40, LDB = 136;
    static constexpr int ASZ = BM * LDA, BSZ = BK * LDB;
};

__device__ __forceinline__ void gemm_mainloop(
    const __half* __restrict__ A, const __half* __restrict__ W,
    int N, int K, int m0, int n0,
    int tid, int wid, int lane, float acc[4][8][4], __half* smh)
{
    using GC = GemmCore;
    const uint32_t sA = (uint32_t)__cvta_generic_to_shared(smh);
    const uint32_t sB = sA + (uint32_t)(GC::STAGES * GC::ASZ) * 2u;
    const int wm = (wid >> 1) * 64;
    const int wn = (wid & 1) * 64;
    const int lrow = lane & 15;
    const int lcol = (lane >> 4) * 8;

    auto load_stage = [&](int s, int k0) {
        uint32_t ab = sA + (uint32_t)(s * GC::ASZ) * 2u;
        uint32_t bb = sB + (uint32_t)(s * GC::BSZ) * 2u;
        #pragma unroll
        for (int it = 0; it < 4; ++it) {
            int e = tid + it * GC::NT;
            int r = e >> 2, c = (e & 3) * 8;
            cp_async16(ab + (uint32_t)(r * GC::LDA + c) * 2u, A + (size_t)(m0 + r) * K + k0 + c);
        }
        #pragma unroll
        for (int it = 0; it < 4; ++it) {
            int e = tid + it * GC::NT;
            int r = e >> 4, c = (e & 15) * 8;
            cp_async16(bb + (uint32_t)(r * GC::LDB + c) * 2u, W + (size_t)(k0 + r) * N + n0 + c);
        }
        cp_async_commit();
    };

    const int nIter = K / GC::BK;
    load_stage(0, 0);
    load_stage(1, GC::BK);
    load_stage(2, 2 * GC::BK);

    for (int it = 0; it < nIter; ++it) {
        cp_async_wait2();
        __syncthreads();

        int nld = it + GC::STAGES - 1;
        if (nld < nIter) load_stage(nld % GC::STAGES, nld * GC::BK);
        else             cp_async_commit();   // keep committed = it+3 invariant

        const int s = it % GC::STAGES;
        const uint32_t Ab = sA + (uint32_t)(s * GC::ASZ) * 2u;
        const uint32_t Bb = sB + (uint32_t)(s * GC::BSZ) * 2u;

        #pragma unroll
        for (int kk = 0; kk < 2; ++kk) {
            uint32_t af[4][4];
            #pragma unroll
            for (int mt = 0; mt < 4; ++mt)
                ldmx4(af[mt][0], af[mt][1], af[mt][2], af[mt][3],
                      Ab + (uint32_t)((wm + mt * 16 + lrow) * GC::LDA + kk * 16 + lcol) * 2u);
            uint32_t bf[16];
            #pragma unroll
            for (int p = 0; p < 4; ++p)
                ldmx4t(bf[p * 4 + 0], bf[p * 4 + 1], bf[p * 4 + 2], bf[p * 4 + 3],
                       Bb + (uint32_t)((kk * 16 + lrow) * GC::LDB + wn + p * 16 + lcol) * 2u);
            #pragma unroll
            for (int nt = 0; nt < 8; ++nt) {
                uint32_t b0 = bf[(nt >> 1) * 4 + (nt & 1) * 2    ];
                uint32_t b1 = bf[(nt >> 1) * 4 + (nt & 1) * 2 + 1];
                #pragma unroll
                for (int mt = 0; mt < 4; ++mt)
                    mma_f16(acc[mt][nt], af[mt], b0, b1);
            }
        }
    }
}

// ---------------------------------------------------------------------------
// Fused Q/K/V projection: blockIdx.x in [0,24): Q 16 / K 4 / V 4 n-blocks.
// ---------------------------------------------------------------------------
__global__ __launch_bounds__(128, 2)
void proj_qkv(const __half* __restrict__ hq, const __half* __restrict__ hk, const __half* __restrict__ hv,
              const __half* __restrict__ hWq, const __half* __restrict__ hWk, const __half* __restrict__ hWv,
              __half* __restrict__ qh, __half* __restrict__ kh, __half* __restrict__ vh)
{
    extern __shared__ __half smh[];
    const int tid  = threadIdx.x;
    const int lane = tid & 31;
    const int wid  = tid >> 5;
    const int g    = lane >> 2;
    const int tg   = lane & 3;

    const int bx = blockIdx.x;
    const __half *A, *W; __half* C; int N, H, nb;
    if (bx < 16)      { A = hq; W = hWq; C = qh; N = EMB;      H = NH;  nb = bx; }
    else if (bx < 20) { A = hk; W = hWk; C = kh; N = NKV * DH; H = NKV; nb = bx - 16; }
    else              { A = hv; W = hWv; C = vh; N = NKV * DH; H = NKV; nb = bx - 20; }

    const int m0 = blockIdx.y * 128;
    const int n0 = nb * 128;
    const int wm = (wid >> 1) * 64;
    const int wn = (wid & 1) * 64;

    float acc[4][8][4];
    #pragma unroll
    for (int i = 0; i < 4; i++)
        #pragma unroll
        for (int j = 0; j < 8; j++)
            #pragma unroll
            for (int r = 0; r < 4; r++) acc[i][j][r] = 0.0f;

    gemm_mainloop(A, W, N, EMB, m0, n0, tid, wid, lane, acc, smh);

    #pragma unroll
    for (int mt = 0; mt < 4; ++mt) {
        int r0 = m0 + wm + mt * 16 + g;
        #pragma unroll
        for (int nt = 0; nt < 8; ++nt) {
            int c = n0 + wn + nt * 8 + 2 * tg;
            int hh = c >> 7, dd = c & (DH - 1);
            {
                int bb = r0 >> 11, ss = r0 & (Sn - 1);
                __half2 t = __floats2half2_rn(acc[mt][nt][0], acc[mt][nt][1]);
                *reinterpret_cast<__half2*>(C + (((size_t)bb * H + hh) * Sn + ss) * DH + dd) = t;
            }
            {
                int r1 = r0 + 8;
                int bb = r1 >> 11, ss = r1 & (Sn - 1);
                __half2 t = __floats2half2_rn(acc[mt][nt][2], acc[mt][nt][3]);
                *reinterpret_cast<__half2*>(C + (((size_t)bb * H + hh) * Sn + ss) * DH + dd) = t;
            }
        }
    }
}

// ---------------------------------------------------------------------------
// Output projection: fp32 row-major out.
// ---------------------------------------------------------------------------
__global__ __launch_bounds__(128, 2)
void proj_out(const __half* __restrict__ A, const __half* __restrict__ W,
              float* __restrict__ C, int M, int N, int K)
{
    extern __shared__ __half smh[];
    const int tid  = threadIdx.x;
    const int lane = tid & 31;
    const int wid  = tid >> 5;
    const int g    = lane >> 2;
    const int tg   = lane & 3;
    const int m0 = blockIdx.y * 128;
    const int n0 = blockIdx.x * 128;
    const int wm = (wid >> 1) * 64;
    const int wn = (wid & 1) * 64;

    float acc[4][8][4];
    #pragma unroll
    for (int i = 0; i < 4; i++)
        #pragma unroll
        for (int j = 0; j < 8; j++)
            #pragma unroll
            for (int r = 0; r < 4; r++) acc[i][j][r] = 0.0f;

    gemm_mainloop(A, W, N, K, m0, n0, tid, wid, lane, acc, smh);

    #pragma unroll
    for (int mt = 0; mt < 4; ++mt) {
        int r0 = m0 + wm + mt * 16 + g;
        #pragma unroll
        for (int nt = 0; nt < 8; ++nt) {
            int c = n0 + wn + nt * 8 + 2 * tg;
            *reinterpret_cast<float2*>(C + (size_t)r0 * N + c) =
                make_float2(acc[mt][nt][0], acc[mt][nt][1]);
            *reinterpret_cast<float2*>(C + (size_t)(r0 + 8) * N + c) =
                make_float2(acc[mt][nt][2], acc[mt][nt][3]);
        }
    }
}

// ---------------------------------------------------------------------------
// Flash attention (fp16 operands, fp32 accum): 128 q-rows/CTA, 64-key tiles,
// 3-stage K/V cp.async pipeline. Base-2 online softmax (log2e folded into Wq);
// causal masking only on the 2 diagonal tiles (uniform branch).
// Grid: (S/128, NH, B).
// ---------------------------------------------------------------------------
#define LDKH 136   // halves per K/V smem row (272B)

__global__ __launch_bounds__(256, 1)
void attn3(const __half* __restrict__ qh, const __half* __restrict__ kh,
           const __half* __restrict__ vh, __half* __restrict__ z)
{
    extern __shared__ __half smh[];
    const int tid  = threadIdx.x;
    const int lane = tid & 31;
    const int w    = tid >> 5;
    const int g    = lane >> 2;
    const int tg   = lane & 3;
    const int lrow = lane & 15;
    const int lcol = (lane >> 4) * 8;

    const int qblk = (int)gridDim.x - 1 - (int)blockIdx.x;  // heavy blocks first
    const int h    = blockIdx.y;
    const int b    = blockIdx.z;
    const int hk   = h >> 2;
    const int q0   = qblk * 128;

    const __half* Qg = qh + (((size_t)b * NH  + h ) * Sn + q0) * DH;
    const __half* Kg = kh + ((size_t)b * NKV + hk) * Sn * DH;
    const __half* Vg = vh + ((size_t)b * NKV + hk) * Sn * DH;

    const uint32_t smbase = (uint32_t)__cvta_generic_to_shared(smh);
    constexpr int BUFF = 2 * 64 * LDKH;

    auto load_kv_async = [&](int bsel, int kt) {
        uint32_t base = smbase + (uint32_t)(bsel * BUFF) * 2u;
        const __half* Kt = Kg + (size_t)kt * 64 * DH;
        const __half* Vt = Vg + (size_t)kt * 64 * DH;
        #pragma unroll
        for (int it = 0; it < 4; ++it) {
            int e = tid + it * 256;
            int r = e >> 4, c = (e & 15) * 8;
            cp_async16(base + (uint32_t)(r * LDKH + c) * 2u,        Kt + (size_t)r * DH + c);
            cp_async16(base + (uint32_t)((64 + r) * LDKH + c) * 2u, Vt + (size_t)r * DH + c);
        }
        cp_async_commit();
    };

    const int ktmax = 2 * qblk + 1;

    load_kv_async(0, 0);
    load_kv_async(1, 1);

    uint32_t Qa[8][4];
    {
        const __half* qw = Qg + (size_t)(w * 16) * DH;
        #pragma unroll
        for (int ks = 0; ks < 8; ++ks) {
            Qa[ks][0] = *reinterpret_cast<const uint32_t*>(qw + (size_t)(g    ) * DH + ks * 16 + 2 * tg);
            Qa[ks][1] = *reinterpret_cast<const uint32_t*>(qw + (size_t)(g + 8) * DH + ks * 16 + 2 * tg);
            Qa[ks][2] = *reinterpret_cast<const uint32_t*>(qw + (size_t)(g    ) * DH + ks * 16 + 8 + 2 * tg);
            Qa[ks][3] = *reinterpret_cast<const uint32_t*>(qw + (size_t)(g + 8) * DH + ks * 16 + 8 + 2 * tg);
        }
    }

    float O[16][4];
    #pragma unroll
    for (int nv = 0; nv < 16; ++nv)
        #pragma unroll
        for (int i = 0; i < 4; ++i) O[nv][i] = 0.0f;
    float m0 = -1e30f, m1 = -1e30f, l0 = 0.0f, l1 = 0.0f;

    for (int kt = 0; kt <= ktmax; ++kt) {
        cp_async_wait1();
        __syncthreads();

        int nk = kt + 2;
        if (nk <= ktmax) load_kv_async(nk % 3, nk);
        else             cp_async_commit();

        const uint32_t Ksb = smbase + (uint32_t)((kt % 3) * BUFF) * 2u;
        const uint32_t Vsb = Ksb + (uint32_t)(64 * LDKH) * 2u;

        // ---- S = Q K^T (base-2 logits; log2e folded into Wq) ----
        float S[8][4];
        #pragma unroll
        for (int n = 0; n < 8; ++n)
            #pragma unroll
            for (int i = 0; i < 4; ++i) S[n][i] = 0.0f;

        #pragma unroll
        for (int kd = 0; kd < 8; ++kd) {
            uint32_t bf[16];
            #pragma unroll
            for (int p = 0; p < 4; ++p)
                ldmx4(bf[p * 4 + 0], bf[p * 4 + 1], bf[p * 4 + 2], bf[p * 4 + 3],
                      Ksb + (uint32_t)((p * 16 + lrow) * LDKH + kd * 16 + lcol) * 2u);
            #pragma unroll
            for (int n = 0; n < 8; ++n) {
                uint32_t b0 = bf[(n >> 1) * 4 + (n & 1)    ];
                uint32_t b1 = bf[(n >> 1) * 4 + (n & 1) + 2];
                mma_f16(S[n], Qa[kd], b0, b1);
            }
        }

        // ---- online softmax (base 2); mask only on diagonal tiles ----
        float mx0 = -1e30f, mx1 = -1e30f;
        if (kt >= 2 * qblk) {
            const int grow0 = q0 + w * 16 + g;
            const int grow1 = grow0 + 8;
            const int kb = kt * 64;
            #pragma unroll
            for (int n = 0; n < 8; ++n) {
                int c = kb + n * 8 + 2 * tg;
                if (c     > grow0) S[n][0] = -1e30f;
                if (c + 1 > grow0) S[n][1] = -1e30f;
                if (c     > grow1) S[n][2] = -1e30f;
                if (c + 1 > grow1) S[n][3] = -1e30f;
                mx0 = fmaxf(mx0, fmaxf(S[n][0], S[n][1]));
                mx1 = fmaxf(mx1, fmaxf(S[n][2], S[n][3]));
            }
        } else {
            #pragma unroll
            for (int n = 0; n < 8; ++n) {
                mx0 = fmaxf(mx0, fmaxf(S[n][0], S[n][1]));
                mx1 = fmaxf(mx1, fmaxf(S[n][2], S[n][3]));
            }
        }
        mx0 = fmaxf(mx0, __shfl_xor_sync(0xffffffffu, mx0, 1));
        mx0 = fmaxf(mx0, __shfl_xor_sync(0xffffffffu, mx0, 2));
        mx1 = fmaxf(mx1, __shfl_xor_sync(0xffffffffu, mx1, 1));
        mx1 = fmaxf(mx1, __shfl_xor_sync(0xffffffffu, mx1, 2));

        float mn0 = fmaxf(m0, mx0), mn1 = fmaxf(m1, mx1);
        float al0 = ex2f(m0 - mn0), al1 = ex2f(m1 - mn1);
        m0 = mn0; m1 = mn1;

        float s0 = 0.0f, s1 = 0.0f;
        #pragma unroll
        for (int n = 0; n < 8; ++n) {
            S[n][0] = ex2f(S[n][0] - mn0); s0 += S[n][0];
            S[n][1] = ex2f(S[n][1] - mn0); s0 += S[n][1];
            S[n][2] = ex2f(S[n][2] - mn1); s1 += S[n][2];
            S[n][3] = ex2f(S[n][3] - mn1); s1 += S[n][3];
        }
        s0 += __shfl_xor_sync(0xffffffffu, s0, 1);
        s0 += __shfl_xor_sync(0xffffffffu, s0, 2);
        s1 += __shfl_xor_sync(0xffffffffu, s1, 1);
        s1 += __shfl_xor_sync(0xffffffffu, s1, 2);
        l0 = l0 * al0 + s0;
        l1 = l1 * al1 + s1;

        #pragma unroll
        for (int nv = 0; nv < 16; ++nv) {
            O[nv][0] *= al0; O[nv][1] *= al0;
            O[nv][2] *= al1; O[nv][3] *= al1;
        }

        // ---- O += P V : C-frag -> A-frag identity; V via ldmatrix.trans ----
        #pragma unroll
        for (int ks = 0; ks < 4; ++ks) {
            uint32_t a[4];
            a[0] = packh2(S[2 * ks    ][0], S[2 * ks    ][1]);
            a[1] = packh2(S[2 * ks    ][2], S[2 * ks    ][3]);
            a[2] = packh2(S[2 * ks + 1][0], S[2 * ks + 1][1]);
            a[3] = packh2(S[2 * ks + 1][2], S[2 * ks + 1][3]);
            #pragma unroll
            for (int p = 0; p < 8; ++p) {
                uint32_t r0, r1, r2, r3;
                ldmx4t(r0, r1, r2, r3,
                       Vsb + (uint32_t)((ks * 16 + lrow) * LDKH + p * 16 + lcol) * 2u);
                mma_f16(O[2 * p    ], a, r0, r1);
                mma_f16(O[2 * p + 1], a, r2, r3);
            }
        }
    }

    // ---- normalize and write Z (fp16) ----
    float inv0 = 1.0f / l0;
    float inv1 = 1.0f / l1;
    __half* zp = z + ((size_t)b * Sn + q0 + w * 16) * (NH * DH) + h * DH;
    #pragma unroll
    for (int nv = 0; nv < 16; ++nv) {
        int c = nv * 8 + 2 * tg;
        __half2 v0 = __floats2half2_rn(O[nv][0] * inv0, O[nv][1] * inv0);
        __half2 v1 = __floats2half2_rn(O[nv][2] * inv1, O[nv][3] * inv1);
        *reinterpret_cast<__half2*>(zp + (size_t)(g    ) * (NH * DH) + c) = v0;
        *reinterpret_cast<__half2*>(zp + (size_t)(g + 8) * (NH * DH) + c) = v1;
    }
}

// ---------------------------------------------------------------------------
extern "C" void kernel_launch(void* const* d_in, const int* in_sizes, int n_in,
                              void* d_out, int out_size)
{
    const float* q  = (const float*)d_in[0];
    const float* k  = (const float*)d_in[1];
    const float* v  = (const float*)d_in[2];
    const float* Wq = (const float*)d_in[3];
    const float* Wk = (const float*)d_in[4];
    const float* Wv = (const float*)d_in[5];
    const float* Wo = (const float*)d_in[6];
    float* out = (float*)d_out;

    __half *hq, *hk, *hv, *hWq, *hWk, *hWv, *hWo, *qh, *khp, *vhp, *zbuf;
    cudaGetSymbolAddress((void**)&hq,  g_hq);
    cudaGetSymbolAddress((void**)&hk,  g_hk);
    cudaGetSymbolAddress((void**)&hv,  g_hv);
    cudaGetSymbolAddress((void**)&hWq, g_hWq);
    cudaGetSymbolAddress((void**)&hWk, g_hWk);
    cudaGetSymbolAddress((void**)&hWv, g_hWv);
    cudaGetSymbolAddress((void**)&hWo, g_hWo);
    cudaGetSymbolAddress((void**)&qh,  g_qh);
    cudaGetSymbolAddress((void**)&khp, g_kh);
    cudaGetSymbolAddress((void**)&vhp, g_vh);
    cudaGetSymbolAddress((void**)&zbuf, g_z);

    const float scaleK = 0.29730177875068026f;                 // 128^-0.25
    const float scaleQ = (float)(0.29730177875068026 * 1.4426950408889634);  // * log2(e)

    {
        long total = CVT_TOTAL;
        int blocks = (int)((total + 255) / 256);
        cvt_all<<<blocks, 256>>>(
            (const float4*)q, (const float4*)k, (const float4*)v,
            (const float4*)Wq, (const float4*)Wk, (const float4*)Wv, (const float4*)Wo,
            (uint2*)hq, (uint2*)hk, (uint2*)hv, (uint2*)hWq, (uint2*)hWk, (uint2*)hWv, (uint2*)hWo,
            scaleQ, scaleK);
    }

    const int smemGemm = GemmCore::STAGES * (GemmCore::ASZ + GemmCore::BSZ) * (int)sizeof(__half); // 75776
    cudaFuncSetAttribute(proj_qkv, cudaFuncAttributeMaxDynamicSharedMemorySize, smemGemm);
    cudaFuncSetAttribute(proj_out, cudaFuncAttributeMaxDynamicSharedMemorySize, smemGemm);
    const int smemAttn = 3 * 2 * 64 * LDKH * (int)sizeof(__half);  // 104448
    cudaFuncSetAttribute(attn3, cudaFuncAttributeMaxDynamicSharedMemorySize, smemAttn);

    proj_qkv<<<dim3(24, MROWS / 128), 128, smemGemm>>>(hq, hk, hv, hWq, hWk, hWv, qh, khp, vhp);

    attn3<<<dim3(Sn / 128, NH, Bn), 256, smemAttn>>>(qh, khp, vhp, zbuf);

    proj_out<<<dim3(EMB / 128, MROWS / 128), 128, smemGemm>>>(zbuf, hWo, out, MROWS, EMB, EMB);
}